// round 1
// baseline (speedup 1.0000x reference)
#include <cuda_runtime.h>
#include <math.h>

#define Bb 8
#define Tt 32
#define Gg 32
#define Ee 768
#define Hh 12
#define Ll 4
#define Ss (Tt*Gg)        // 1024
#define HD_ (Ee/Hh)       // 64
#define NR (Bb*Ss)        // 8192 rows

// ---------------- scratch (device globals; no cudaMalloc allowed) ------------
__device__ float g_h[NR*Ee];          // residual stream
__device__ float g_y[NR*Ee];          // ln output / attention output
__device__ float g_qkv[NR*3*Ee];      // qkv
__device__ float g_fc[NR*4*Ee];       // mlp hidden

// ---------------- embed: h = x + wpe[clip(date)] broadcast over G ------------
__global__ void embed_kernel(const float* __restrict__ x,
                             const int* __restrict__ date,
                             const float* __restrict__ wpe) {
    int idx = blockIdx.x * blockDim.x + threadIdx.x;
    if (idx >= NR * Ee) return;
    int e   = idx % Ee;
    int row = idx / Ee;          // b*S + s
    int b   = row / Ss;
    int s   = row % Ss;
    int t   = s / Gg;
    int d   = date[b * Tt + t];
    d = min(max(d, 0), 49);
    g_h[idx] = x[idx] + wpe[d * Ee + e];
}

// ---------------- layernorm: one block per row -------------------------------
__global__ void ln_kernel(const float* __restrict__ in, float* __restrict__ out,
                          const float* __restrict__ w, const float* __restrict__ bia) {
    int row = blockIdx.x;
    const float* xr = in + (size_t)row * Ee;
    __shared__ float red[256];
    int tid = threadIdx.x;
    float s = 0.f;
    for (int e = tid; e < Ee; e += 256) s += xr[e];
    red[tid] = s; __syncthreads();
    for (int o = 128; o > 0; o >>= 1) { if (tid < o) red[tid] += red[tid + o]; __syncthreads(); }
    float mean = red[0] / Ee;
    __syncthreads();
    float v = 0.f;
    for (int e = tid; e < Ee; e += 256) { float d = xr[e] - mean; v += d * d; }
    red[tid] = v; __syncthreads();
    for (int o = 128; o > 0; o >>= 1) { if (tid < o) red[tid] += red[tid + o]; __syncthreads(); }
    float rstd = rsqrtf(red[0] / Ee + 1e-5f);
    for (int e = tid; e < Ee; e += 256)
        out[(size_t)row * Ee + e] = (xr[e] - mean) * rstd * w[e] + bia[e];
}

// ---------------- GEMM: C[m,n] (op)= sum_k A[m,k]*W[n,k] + bias[n] -----------
// 128x128 block tile, BK=8, 256 threads, 8x8 per thread (2x2 of 4x4 frags).
// EPI: 0 = store, 1 = NewGELU(store), 2 = add into C (residual)
template<int EPI>
__global__ void __launch_bounds__(256)
gemm_kernel(const float* __restrict__ A, const float* __restrict__ W,
            const float* __restrict__ bias, float* __restrict__ C,
            int M, int N, int K) {
    __shared__ __align__(16) float As[8][132];
    __shared__ __align__(16) float Ws[8][132];
    const int m0 = blockIdx.y * 128;
    const int n0 = blockIdx.x * 128;
    const int tid = threadIdx.x;
    const int tx = tid & 15;         // 0..15 -> n
    const int ty = tid >> 4;         // 0..15 -> m

    // global-load coords: one float4 per matrix per k-tile
    const int lr = tid >> 1;         // row in tile 0..127
    const int lc = (tid & 1) * 4;    // col 0 or 4

    float acc[2][2][4][4];
    #pragma unroll
    for (int a = 0; a < 2; a++)
        #pragma unroll
        for (int b = 0; b < 2; b++)
            #pragma unroll
            for (int i = 0; i < 4; i++)
                #pragma unroll
                for (int j = 0; j < 4; j++) acc[a][b][i][j] = 0.f;

    for (int k0 = 0; k0 < K; k0 += 8) {
        float4 av = *(const float4*)&A[(size_t)(m0 + lr) * K + k0 + lc];
        float4 wv = *(const float4*)&W[(size_t)(n0 + lr) * K + k0 + lc];
        As[lc + 0][lr] = av.x; As[lc + 1][lr] = av.y;
        As[lc + 2][lr] = av.z; As[lc + 3][lr] = av.w;
        Ws[lc + 0][lr] = wv.x; Ws[lc + 1][lr] = wv.y;
        Ws[lc + 2][lr] = wv.z; Ws[lc + 3][lr] = wv.w;
        __syncthreads();
        #pragma unroll
        for (int kk = 0; kk < 8; kk++) {
            float4 a0 = *(const float4*)&As[kk][ty * 4];
            float4 a1 = *(const float4*)&As[kk][64 + ty * 4];
            float4 b0 = *(const float4*)&Ws[kk][tx * 4];
            float4 b1 = *(const float4*)&Ws[kk][64 + tx * 4];
            float af[2][4] = {{a0.x, a0.y, a0.z, a0.w}, {a1.x, a1.y, a1.z, a1.w}};
            float bf[2][4] = {{b0.x, b0.y, b0.z, b0.w}, {b1.x, b1.y, b1.z, b1.w}};
            #pragma unroll
            for (int a = 0; a < 2; a++)
                #pragma unroll
                for (int b = 0; b < 2; b++)
                    #pragma unroll
                    for (int i = 0; i < 4; i++)
                        #pragma unroll
                        for (int j = 0; j < 4; j++)
                            acc[a][b][i][j] += af[a][i] * bf[b][j];
        }
        __syncthreads();
    }

    #pragma unroll
    for (int a = 0; a < 2; a++) {
        #pragma unroll
        for (int i = 0; i < 4; i++) {
            int m = m0 + a * 64 + ty * 4 + i;
            #pragma unroll
            for (int b = 0; b < 2; b++) {
                #pragma unroll
                for (int j = 0; j < 4; j++) {
                    int n = n0 + b * 64 + tx * 4 + j;
                    float v = acc[a][b][i][j] + bias[n];
                    size_t o = (size_t)m * N + n;
                    if (EPI == 0) {
                        C[o] = v;
                    } else if (EPI == 1) {
                        float v3 = v * v * v;
                        C[o] = 0.5f * v * (1.0f + tanhf(0.7978845608028654f * (v + 0.044715f * v3)));
                    } else {
                        C[o] += v;
                    }
                }
            }
        }
    }
}

// ---------------- attention: one block per (b, h, q-row) ---------------------
// block-causal: query s (block tq = s/G) attends to keys j < (tq+1)*G
__global__ void __launch_bounds__(128)
attn_kernel(const float* __restrict__ qkv, float* __restrict__ out) {
    const int s = blockIdx.x, h = blockIdx.y, b = blockIdx.z;
    const int tid = threadIdx.x;
    const int tq = s / Gg;
    const int kmax = (tq + 1) * Gg;

    __shared__ float qv[64];
    __shared__ float sc[Ss];
    __shared__ float kt[64][65];
    __shared__ float red[128];

    const size_t rowq = (size_t)(b * Ss + s) * 3 * Ee + h * HD_;
    if (tid < 64) qv[tid] = qkv[rowq + tid];
    __syncthreads();

    // scores
    for (int j0 = 0; j0 < kmax; j0 += 64) {
        int nk = min(64, kmax - j0);
        for (int idx = tid; idx < nk * 64; idx += 128) {
            int r = idx >> 6, c = idx & 63;
            kt[r][c] = qkv[(size_t)(b * Ss + j0 + r) * 3 * Ee + Ee + h * HD_ + c];
        }
        __syncthreads();
        if (tid < nk) {
            float a = 0.f;
            #pragma unroll 16
            for (int d = 0; d < 64; d++) a += qv[d] * kt[tid][d];
            sc[j0 + tid] = a * 0.125f;   // 1/sqrt(64)
        }
        __syncthreads();
    }

    // softmax over sc[0..kmax)
    float m = -1e30f;
    for (int j = tid; j < kmax; j += 128) m = fmaxf(m, sc[j]);
    red[tid] = m; __syncthreads();
    for (int o = 64; o > 0; o >>= 1) { if (tid < o) red[tid] = fmaxf(red[tid], red[tid + o]); __syncthreads(); }
    m = red[0]; __syncthreads();
    float ssum = 0.f;
    for (int j = tid; j < kmax; j += 128) { float p = __expf(sc[j] - m); sc[j] = p; ssum += p; }
    red[tid] = ssum; __syncthreads();
    for (int o = 64; o > 0; o >>= 1) { if (tid < o) red[tid] += red[tid + o]; __syncthreads(); }
    float inv = 1.f / red[0];

    // o = P @ V
    float o_acc = 0.f;
    for (int j0 = 0; j0 < kmax; j0 += 64) {
        int nk = min(64, kmax - j0);
        __syncthreads();
        for (int idx = tid; idx < nk * 64; idx += 128) {
            int r = idx >> 6, c = idx & 63;
            kt[r][c] = qkv[(size_t)(b * Ss + j0 + r) * 3 * Ee + 2 * Ee + h * HD_ + c];
        }
        __syncthreads();
        if (tid < 64) {
            #pragma unroll 8
            for (int r = 0; r < nk; r++) o_acc += sc[j0 + r] * kt[r][tid];
        }
    }
    if (tid < 64) out[(size_t)(b * Ss + s) * Ee + h * HD_ + tid] = o_acc * inv;
}

// ---------------- host orchestration -----------------------------------------
extern "C" void kernel_launch(void* const* d_in, const int* in_sizes, int n_in,
                              void* d_out, int out_size) {
    const float* x      = (const float*)d_in[0];
    const int*   date   = (const int*)  d_in[1];
    const float* wpe    = (const float*)d_in[2];
    const float* ln1_w  = (const float*)d_in[3];
    const float* ln1_b  = (const float*)d_in[4];
    const float* in_w   = (const float*)d_in[5];
    const float* in_b   = (const float*)d_in[6];
    const float* out_w  = (const float*)d_in[7];
    const float* out_b  = (const float*)d_in[8];
    const float* ln2_w  = (const float*)d_in[9];
    const float* ln2_b  = (const float*)d_in[10];
    const float* fc_w   = (const float*)d_in[11];
    const float* fc_b   = (const float*)d_in[12];
    const float* proj_w = (const float*)d_in[13];
    const float* proj_b = (const float*)d_in[14];
    const float* lnf_w  = (const float*)d_in[15];
    const float* lnf_b  = (const float*)d_in[16];
    float* out = (float*)d_out;

    float *h, *y, *qkv, *fc;
    cudaGetSymbolAddress((void**)&h,   g_h);
    cudaGetSymbolAddress((void**)&y,   g_y);
    cudaGetSymbolAddress((void**)&qkv, g_qkv);
    cudaGetSymbolAddress((void**)&fc,  g_fc);

    // embed
    embed_kernel<<<(NR * Ee + 255) / 256, 256>>>(x, date, wpe);

    for (int l = 0; l < Ll; l++) {
        // LN1
        ln_kernel<<<NR, 256>>>(h, y, ln1_w + (size_t)l * Ee, ln1_b + (size_t)l * Ee);
        // QKV = y @ in_w^T + in_b    [8192, 2304]
        gemm_kernel<0><<<dim3(3 * Ee / 128, NR / 128), 256>>>(
            y, in_w + (size_t)l * 3 * Ee * Ee, in_b + (size_t)l * 3 * Ee, qkv,
            NR, 3 * Ee, Ee);
        // attention -> y
        attn_kernel<<<dim3(Ss, Hh, Bb), 128>>>(qkv, y);
        // h += y @ out_w^T + out_b
        gemm_kernel<2><<<dim3(Ee / 128, NR / 128), 256>>>(
            y, out_w + (size_t)l * Ee * Ee, out_b + (size_t)l * Ee, h,
            NR, Ee, Ee);
        // LN2
        ln_kernel<<<NR, 256>>>(h, y, ln2_w + (size_t)l * Ee, ln2_b + (size_t)l * Ee);
        // fc = gelu(y @ fc_w^T + fc_b)   [8192, 3072]
        gemm_kernel<1><<<dim3(4 * Ee / 128, NR / 128), 256>>>(
            y, fc_w + (size_t)l * 4 * Ee * Ee, fc_b + (size_t)l * 4 * Ee, fc,
            NR, 4 * Ee, Ee);
        // h += fc @ proj_w^T + proj_b
        gemm_kernel<2><<<dim3(Ee / 128, NR / 128), 256>>>(
            fc, proj_w + (size_t)l * Ee * 4 * Ee, proj_b + (size_t)l * Ee, h,
            NR, Ee, 4 * Ee);
    }

    // final LN -> out
    ln_kernel<<<NR, 256>>>(h, out, lnf_w, lnf_b);
}

// round 2
// speedup vs baseline: 1.3933x; 1.3933x over previous
#include <cuda_runtime.h>
#include <math.h>

#define Bb 8
#define Tt 32
#define Gg 32
#define Ee 768
#define Hh 12
#define Ll 4
#define Ss (Tt*Gg)        // 1024
#define HD_ (Ee/Hh)       // 64
#define NR (Bb*Ss)        // 8192 rows

// ---------------- scratch (device globals; no cudaMalloc allowed) ------------
__device__ float g_h[NR*Ee];          // residual stream
__device__ float g_y[NR*Ee];          // ln output / attention output
__device__ float g_qkv[NR*3*Ee];      // qkv
__device__ float g_fc[NR*4*Ee];       // mlp hidden

// ---------------- embed: h = x + wpe[clip(date)] broadcast over G ------------
__global__ void embed_kernel(const float* __restrict__ x,
                             const int* __restrict__ date,
                             const float* __restrict__ wpe) {
    int idx = blockIdx.x * blockDim.x + threadIdx.x;
    if (idx >= NR * Ee) return;
    int e   = idx % Ee;
    int row = idx / Ee;          // b*S + s
    int b   = row / Ss;
    int s   = row % Ss;
    int t   = s / Gg;
    int d   = date[b * Tt + t];
    d = min(max(d, 0), 49);
    g_h[idx] = x[idx] + wpe[d * Ee + e];
}

// ---------------- layernorm: one block per row -------------------------------
__global__ void ln_kernel(const float* __restrict__ in, float* __restrict__ out,
                          const float* __restrict__ w, const float* __restrict__ bia) {
    int row = blockIdx.x;
    const float* xr = in + (size_t)row * Ee;
    __shared__ float red[256];
    int tid = threadIdx.x;
    float s = 0.f;
    for (int e = tid; e < Ee; e += 256) s += xr[e];
    red[tid] = s; __syncthreads();
    for (int o = 128; o > 0; o >>= 1) { if (tid < o) red[tid] += red[tid + o]; __syncthreads(); }
    float mean = red[0] / Ee;
    __syncthreads();
    float v = 0.f;
    for (int e = tid; e < Ee; e += 256) { float d = xr[e] - mean; v += d * d; }
    red[tid] = v; __syncthreads();
    for (int o = 128; o > 0; o >>= 1) { if (tid < o) red[tid] += red[tid + o]; __syncthreads(); }
    float rstd = rsqrtf(red[0] / Ee + 1e-5f);
    for (int e = tid; e < Ee; e += 256)
        out[(size_t)row * Ee + e] = (xr[e] - mean) * rstd * w[e] + bia[e];
}

// ---------------- tf32 tensor-core GEMM --------------------------------------
// C[m,n] (op)= sum_k A[m,k]*W[n,k] + bias[n]
// 128x128 block tile, BK=16, 256 threads = 8 warps (2 m-rows x 4 n-cols),
// warp tile 64x32 = 4x4 of m16n8k8 tf32 MMA fragments.
// EPI: 0 = store, 1 = NewGELU(store), 2 = add into C (residual)

__device__ __forceinline__ unsigned f2tf(float f) {
    unsigned u;
    asm("cvt.rna.tf32.f32 %0, %1;" : "=r"(u) : "f"(f));
    return u;
}

template<int EPI>
__global__ void __launch_bounds__(256)
gemm_tc(const float* __restrict__ A, const float* __restrict__ W,
        const float* __restrict__ bias, float* __restrict__ C,
        int M, int N, int K) {
    __shared__ unsigned As[128][20];   // [m][k] stride 20 -> conflict-free frag reads
    __shared__ unsigned Ws[128][20];   // [n][k]
    const int m0 = blockIdx.y * 128;
    const int n0 = blockIdx.x * 128;
    const int tid  = threadIdx.x;
    const int lane = tid & 31;
    const int wid  = tid >> 5;
    const int wm = (wid & 1) * 64;     // warp row offset
    const int wn = (wid >> 1) * 32;    // warp col offset
    const int gr = lane >> 2;          // 0..7
    const int gc = lane & 3;           // 0..3

    float acc[4][4][4];
    #pragma unroll
    for (int tm = 0; tm < 4; tm++)
        #pragma unroll
        for (int tn = 0; tn < 4; tn++)
            #pragma unroll
            for (int i = 0; i < 4; i++) acc[tm][tn][i] = 0.f;

    for (int k0 = 0; k0 < K; k0 += 16) {
        #pragma unroll
        for (int i = 0; i < 2; i++) {
            int linear = tid + i * 256;          // 0..511
            int r  = linear >> 2;                // 0..127
            int c4 = (linear & 3) * 4;           // 0,4,8,12
            float4 av = *(const float4*)&A[(size_t)(m0 + r) * K + k0 + c4];
            float4 wv = *(const float4*)&W[(size_t)(n0 + r) * K + k0 + c4];
            As[r][c4 + 0] = f2tf(av.x); As[r][c4 + 1] = f2tf(av.y);
            As[r][c4 + 2] = f2tf(av.z); As[r][c4 + 3] = f2tf(av.w);
            Ws[r][c4 + 0] = f2tf(wv.x); Ws[r][c4 + 1] = f2tf(wv.y);
            Ws[r][c4 + 2] = f2tf(wv.z); Ws[r][c4 + 3] = f2tf(wv.w);
        }
        __syncthreads();
        #pragma unroll
        for (int kk = 0; kk < 16; kk += 8) {
            unsigned af[4][4], bf[4][2];
            #pragma unroll
            for (int tm = 0; tm < 4; tm++) {
                int mr = wm + tm * 16 + gr;
                af[tm][0] = As[mr][kk + gc];
                af[tm][1] = As[mr + 8][kk + gc];
                af[tm][2] = As[mr][kk + gc + 4];
                af[tm][3] = As[mr + 8][kk + gc + 4];
            }
            #pragma unroll
            for (int tn = 0; tn < 4; tn++) {
                int nr = wn + tn * 8 + gr;
                bf[tn][0] = Ws[nr][kk + gc];
                bf[tn][1] = Ws[nr][kk + gc + 4];
            }
            #pragma unroll
            for (int tm = 0; tm < 4; tm++)
                #pragma unroll
                for (int tn = 0; tn < 4; tn++)
                    asm volatile(
                        "mma.sync.aligned.m16n8k8.row.col.f32.tf32.tf32.f32 "
                        "{%0,%1,%2,%3}, {%4,%5,%6,%7}, {%8,%9}, {%0,%1,%2,%3};"
                        : "+f"(acc[tm][tn][0]), "+f"(acc[tm][tn][1]),
                          "+f"(acc[tm][tn][2]), "+f"(acc[tm][tn][3])
                        : "r"(af[tm][0]), "r"(af[tm][1]),
                          "r"(af[tm][2]), "r"(af[tm][3]),
                          "r"(bf[tn][0]), "r"(bf[tn][1]));
        }
        __syncthreads();
    }

    // epilogue: acc[tm][tn] = m16n8; c0/c1 at (row, 2gc/2gc+1), c2/c3 at row+8
    #pragma unroll
    for (int tm = 0; tm < 4; tm++) {
        #pragma unroll
        for (int tn = 0; tn < 4; tn++) {
            int m = m0 + wm + tm * 16 + gr;
            int n = n0 + wn + tn * 8 + gc * 2;
            float b0 = bias[n], b1 = bias[n + 1];
            #pragma unroll
            for (int half = 0; half < 2; half++) {
                int mm = m + half * 8;
                float v0 = acc[tm][tn][half * 2 + 0] + b0;
                float v1 = acc[tm][tn][half * 2 + 1] + b1;
                size_t o = (size_t)mm * N + n;
                if (EPI == 0) {
                    C[o] = v0; C[o + 1] = v1;
                } else if (EPI == 1) {
                    float u0 = v0 + 0.044715f * v0 * v0 * v0;
                    float u1 = v1 + 0.044715f * v1 * v1 * v1;
                    C[o]     = 0.5f * v0 * (1.0f + tanhf(0.7978845608028654f * u0));
                    C[o + 1] = 0.5f * v1 * (1.0f + tanhf(0.7978845608028654f * u1));
                } else {
                    C[o] += v0; C[o + 1] += v1;
                }
            }
        }
    }
}

// ---------------- attention: one block per (b, h, q-row) ---------------------
// block-causal: query s (block tq = s/G) attends to keys j < (tq+1)*G
__global__ void __launch_bounds__(128)
attn_kernel(const float* __restrict__ qkv, float* __restrict__ out) {
    const int s = blockIdx.x, h = blockIdx.y, b = blockIdx.z;
    const int tid = threadIdx.x;
    const int tq = s / Gg;
    const int kmax = (tq + 1) * Gg;

    __shared__ float qv[64];
    __shared__ float sc[Ss];
    __shared__ float kt[64][65];
    __shared__ float red[128];

    const size_t rowq = (size_t)(b * Ss + s) * 3 * Ee + h * HD_;
    if (tid < 64) qv[tid] = qkv[rowq + tid];
    __syncthreads();

    // scores
    for (int j0 = 0; j0 < kmax; j0 += 64) {
        int nk = min(64, kmax - j0);
        for (int idx = tid; idx < nk * 64; idx += 128) {
            int r = idx >> 6, c = idx & 63;
            kt[r][c] = qkv[(size_t)(b * Ss + j0 + r) * 3 * Ee + Ee + h * HD_ + c];
        }
        __syncthreads();
        if (tid < nk) {
            float a = 0.f;
            #pragma unroll 16
            for (int d = 0; d < 64; d++) a += qv[d] * kt[tid][d];
            sc[j0 + tid] = a * 0.125f;   // 1/sqrt(64)
        }
        __syncthreads();
    }

    // softmax over sc[0..kmax)
    float m = -1e30f;
    for (int j = tid; j < kmax; j += 128) m = fmaxf(m, sc[j]);
    red[tid] = m; __syncthreads();
    for (int o = 64; o > 0; o >>= 1) { if (tid < o) red[tid] = fmaxf(red[tid], red[tid + o]); __syncthreads(); }
    m = red[0]; __syncthreads();
    float ssum = 0.f;
    for (int j = tid; j < kmax; j += 128) { float p = __expf(sc[j] - m); sc[j] = p; ssum += p; }
    red[tid] = ssum; __syncthreads();
    for (int o = 64; o > 0; o >>= 1) { if (tid < o) red[tid] += red[tid + o]; __syncthreads(); }
    float inv = 1.f / red[0];

    // o = P @ V
    float o_acc = 0.f;
    for (int j0 = 0; j0 < kmax; j0 += 64) {
        int nk = min(64, kmax - j0);
        __syncthreads();
        for (int idx = tid; idx < nk * 64; idx += 128) {
            int r = idx >> 6, c = idx & 63;
            kt[r][c] = qkv[(size_t)(b * Ss + j0 + r) * 3 * Ee + 2 * Ee + h * HD_ + c];
        }
        __syncthreads();
        if (tid < 64) {
            #pragma unroll 8
            for (int r = 0; r < nk; r++) o_acc += sc[j0 + r] * kt[r][tid];
        }
    }
    if (tid < 64) out[(size_t)(b * Ss + s) * Ee + h * HD_ + tid] = o_acc * inv;
}

// ---------------- host orchestration -----------------------------------------
extern "C" void kernel_launch(void* const* d_in, const int* in_sizes, int n_in,
                              void* d_out, int out_size) {
    const float* x      = (const float*)d_in[0];
    const int*   date   = (const int*)  d_in[1];
    const float* wpe    = (const float*)d_in[2];
    const float* ln1_w  = (const float*)d_in[3];
    const float* ln1_b  = (const float*)d_in[4];
    const float* in_w   = (const float*)d_in[5];
    const float* in_b   = (const float*)d_in[6];
    const float* out_w  = (const float*)d_in[7];
    const float* out_b  = (const float*)d_in[8];
    const float* ln2_w  = (const float*)d_in[9];
    const float* ln2_b  = (const float*)d_in[10];
    const float* fc_w   = (const float*)d_in[11];
    const float* fc_b   = (const float*)d_in[12];
    const float* proj_w = (const float*)d_in[13];
    const float* proj_b = (const float*)d_in[14];
    const float* lnf_w  = (const float*)d_in[15];
    const float* lnf_b  = (const float*)d_in[16];
    float* out = (float*)d_out;

    float *h, *y, *qkv, *fc;
    cudaGetSymbolAddress((void**)&h,   g_h);
    cudaGetSymbolAddress((void**)&y,   g_y);
    cudaGetSymbolAddress((void**)&qkv, g_qkv);
    cudaGetSymbolAddress((void**)&fc,  g_fc);

    // embed
    embed_kernel<<<(NR * Ee + 255) / 256, 256>>>(x, date, wpe);

    for (int l = 0; l < Ll; l++) {
        // LN1
        ln_kernel<<<NR, 256>>>(h, y, ln1_w + (size_t)l * Ee, ln1_b + (size_t)l * Ee);
        // QKV = y @ in_w^T + in_b    [8192, 2304]
        gemm_tc<0><<<dim3(3 * Ee / 128, NR / 128), 256>>>(
            y, in_w + (size_t)l * 3 * Ee * Ee, in_b + (size_t)l * 3 * Ee, qkv,
            NR, 3 * Ee, Ee);
        // attention -> y
        attn_kernel<<<dim3(Ss, Hh, Bb), 128>>>(qkv, y);
        // h += y @ out_w^T + out_b
        gemm_tc<2><<<dim3(Ee / 128, NR / 128), 256>>>(
            y, out_w + (size_t)l * Ee * Ee, out_b + (size_t)l * Ee, h,
            NR, Ee, Ee);
        // LN2
        ln_kernel<<<NR, 256>>>(h, y, ln2_w + (size_t)l * Ee, ln2_b + (size_t)l * Ee);
        // fc = gelu(y @ fc_w^T + fc_b)   [8192, 3072]
        gemm_tc<1><<<dim3(4 * Ee / 128, NR / 128), 256>>>(
            y, fc_w + (size_t)l * 4 * Ee * Ee, fc_b + (size_t)l * 4 * Ee, fc,
            NR, 4 * Ee, Ee);
        // h += fc @ proj_w^T + proj_b
        gemm_tc<2><<<dim3(Ee / 128, NR / 128), 256>>>(
            fc, proj_w + (size_t)l * Ee * 4 * Ee, proj_b + (size_t)l * Ee, h,
            NR, Ee, 4 * Ee);
    }

    // final LN -> out
    ln_kernel<<<NR, 256>>>(h, out, lnf_w, lnf_b);
}

// round 4
// speedup vs baseline: 2.5799x; 1.8516x over previous
#include <cuda_runtime.h>
#include <math.h>

#define Bb 8
#define Tt 32
#define Gg 32
#define Ee 768
#define Hh 12
#define Ll 4
#define Ss (Tt*Gg)        // 1024
#define HD_ (Ee/Hh)       // 64
#define NR (Bb*Ss)        // 8192 rows

// ---------------- scratch (device globals; no cudaMalloc allowed) ------------
__device__ float g_h[NR*Ee];
__device__ float g_y[NR*Ee];
__device__ float g_qkv[NR*3*Ee];
__device__ float g_fc[NR*4*Ee];

// ---------------- embed -------------------------------------------------------
__global__ void embed_kernel(const float* __restrict__ x,
                             const int* __restrict__ date,
                             const float* __restrict__ wpe) {
    int idx = blockIdx.x * blockDim.x + threadIdx.x;
    if (idx >= NR * Ee) return;
    int e   = idx % Ee;
    int row = idx / Ee;
    int b   = row / Ss;
    int s   = row % Ss;
    int t   = s / Gg;
    int d   = date[b * Tt + t];
    d = min(max(d, 0), 49);
    g_h[idx] = x[idx] + wpe[d * Ee + e];
}

// ---------------- layernorm ---------------------------------------------------
__global__ void ln_kernel(const float* __restrict__ in, float* __restrict__ out,
                          const float* __restrict__ w, const float* __restrict__ bia) {
    int row = blockIdx.x;
    const float* xr = in + (size_t)row * Ee;
    __shared__ float red[256];
    int tid = threadIdx.x;
    float s = 0.f;
    for (int e = tid; e < Ee; e += 256) s += xr[e];
    red[tid] = s; __syncthreads();
    for (int o = 128; o > 0; o >>= 1) { if (tid < o) red[tid] += red[tid + o]; __syncthreads(); }
    float mean = red[0] / Ee;
    __syncthreads();
    float v = 0.f;
    for (int e = tid; e < Ee; e += 256) { float d = xr[e] - mean; v += d * d; }
    red[tid] = v; __syncthreads();
    for (int o = 128; o > 0; o >>= 1) { if (tid < o) red[tid] += red[tid + o]; __syncthreads(); }
    float rstd = rsqrtf(red[0] / Ee + 1e-5f);
    for (int e = tid; e < Ee; e += 256)
        out[(size_t)row * Ee + e] = (xr[e] - mean) * rstd * w[e] + bia[e];
}

// ---------------- cp.async helper --------------------------------------------
__device__ __forceinline__ void cp16(void* s, const void* g) {
    unsigned sa = (unsigned)__cvta_generic_to_shared(s);
    asm volatile("cp.async.ca.shared.global [%0], [%1], 16;\n" :: "r"(sa), "l"(g));
}
__device__ __forceinline__ void cp_commit() {
    asm volatile("cp.async.commit_group;\n" ::);
}
template<int N>
__device__ __forceinline__ void cp_wait() {
    asm volatile("cp.async.wait_group %0;\n" :: "n"(N));
}

// ---------------- tf32 tensor-core GEMM, 2-stage cp.async pipeline ----------
// C[m,n] (op)= sum_k A[m,k]*W[n,k] + bias[n]
// 128x128 tile, BK=16, 256 threads = 8 warps (2m x 4n), warp tile 64x32.
// fp32 loaded raw into smem; mma.tf32 consumes fp32-format bits directly.
template<int EPI>
__global__ void __launch_bounds__(256)
gemm_tc(const float* __restrict__ A, const float* __restrict__ W,
        const float* __restrict__ bias, float* __restrict__ C,
        int M, int N, int K) {
    __shared__ float As[2][128][20];
    __shared__ float Ws[2][128][20];
    const int m0 = blockIdx.y * 128;
    const int n0 = blockIdx.x * 128;
    const int tid  = threadIdx.x;
    const int lane = tid & 31;
    const int wid  = tid >> 5;
    const int wm = (wid & 1) * 64;
    const int wn = (wid >> 1) * 32;
    const int gr = lane >> 2;
    const int gc = lane & 3;

    const int KT = K / 16;

    float acc[4][4][4];
    #pragma unroll
    for (int tm = 0; tm < 4; tm++)
        #pragma unroll
        for (int tn = 0; tn < 4; tn++)
            #pragma unroll
            for (int i = 0; i < 4; i++) acc[tm][tn][i] = 0.f;

    // prologue: stage 0
    #pragma unroll
    for (int i = 0; i < 2; i++) {
        int f4 = tid + i * 256;
        int r = f4 >> 2, c = (f4 & 3) * 4;
        cp16(&As[0][r][c], &A[(size_t)(m0 + r) * K + c]);
        cp16(&Ws[0][r][c], &W[(size_t)(n0 + r) * K + c]);
    }
    cp_commit();

    for (int kt = 0; kt < KT; kt++) {
        int buf = kt & 1;
        if (kt + 1 < KT) {
            int k0 = (kt + 1) * 16;
            #pragma unroll
            for (int i = 0; i < 2; i++) {
                int f4 = tid + i * 256;
                int r = f4 >> 2, c = (f4 & 3) * 4;
                cp16(&As[buf ^ 1][r][c], &A[(size_t)(m0 + r) * K + k0 + c]);
                cp16(&Ws[buf ^ 1][r][c], &W[(size_t)(n0 + r) * K + k0 + c]);
            }
            cp_commit();
            cp_wait<1>();
        } else {
            cp_wait<0>();
        }
        __syncthreads();

        #pragma unroll
        for (int kk = 0; kk < 16; kk += 8) {
            unsigned af[4][4], bf[4][2];
            #pragma unroll
            for (int tm = 0; tm < 4; tm++) {
                int mr = wm + tm * 16 + gr;
                af[tm][0] = __float_as_uint(As[buf][mr][kk + gc]);
                af[tm][1] = __float_as_uint(As[buf][mr + 8][kk + gc]);
                af[tm][2] = __float_as_uint(As[buf][mr][kk + gc + 4]);
                af[tm][3] = __float_as_uint(As[buf][mr + 8][kk + gc + 4]);
            }
            #pragma unroll
            for (int tn = 0; tn < 4; tn++) {
                int nr = wn + tn * 8 + gr;
                bf[tn][0] = __float_as_uint(Ws[buf][nr][kk + gc]);
                bf[tn][1] = __float_as_uint(Ws[buf][nr][kk + gc + 4]);
            }
            #pragma unroll
            for (int tm = 0; tm < 4; tm++)
                #pragma unroll
                for (int tn = 0; tn < 4; tn++)
                    asm volatile(
                        "mma.sync.aligned.m16n8k8.row.col.f32.tf32.tf32.f32 "
                        "{%0,%1,%2,%3}, {%4,%5,%6,%7}, {%8,%9}, {%0,%1,%2,%3};"
                        : "+f"(acc[tm][tn][0]), "+f"(acc[tm][tn][1]),
                          "+f"(acc[tm][tn][2]), "+f"(acc[tm][tn][3])
                        : "r"(af[tm][0]), "r"(af[tm][1]),
                          "r"(af[tm][2]), "r"(af[tm][3]),
                          "r"(bf[tn][0]), "r"(bf[tn][1]));
        }
        __syncthreads();
    }

    #pragma unroll
    for (int tm = 0; tm < 4; tm++) {
        #pragma unroll
        for (int tn = 0; tn < 4; tn++) {
            int m = m0 + wm + tm * 16 + gr;
            int n = n0 + wn + tn * 8 + gc * 2;
            float b0 = bias[n], b1 = bias[n + 1];
            #pragma unroll
            for (int half = 0; half < 2; half++) {
                int mm = m + half * 8;
                float v0 = acc[tm][tn][half * 2 + 0] + b0;
                float v1 = acc[tm][tn][half * 2 + 1] + b1;
                size_t o = (size_t)mm * N + n;
                if (EPI == 0) {
                    C[o] = v0; C[o + 1] = v1;
                } else if (EPI == 1) {
                    float u0 = v0 + 0.044715f * v0 * v0 * v0;
                    float u1 = v1 + 0.044715f * v1 * v1 * v1;
                    C[o]     = 0.5f * v0 * (1.0f + tanhf(0.7978845608028654f * u0));
                    C[o + 1] = 0.5f * v1 * (1.0f + tanhf(0.7978845608028654f * u1));
                } else {
                    C[o] += v0; C[o + 1] += v1;
                }
            }
        }
    }
}

// ---------------- flash attention: one block per (b, h, 32-query T-block) ----
// q-tile = G = 32 => every row in tile has identical kmax = (tq+1)*32; no mask.
__global__ void __launch_bounds__(256)
attn_flash(const float* __restrict__ qkv, float* __restrict__ out) {
    const int tq = (Tt - 1) - blockIdx.x;   // heavy tiles first
    const int h = blockIdx.y, b = blockIdx.z;
    const int q0 = tq * Gg;
    const int nkt = tq + 1;
    const int tid = threadIdx.x;

    __shared__ float Qs[32][68], Ks[32][68], Vs[32][68];
    __shared__ float sc[32][33];
    __shared__ float mrow[32], corr_s[32], lrow[32];

    const int qrow  = tid >> 3;      // 0..31
    const int koff  = tid & 7;       // 0..7
    const int dbase = (tid & 7) * 8; // 0..56

    // load Q tile [32 x 64]
    {
        const size_t base = (size_t)(b * Ss + q0) * (3 * Ee) + h * HD_;
        #pragma unroll
        for (int i = 0; i < 2; i++) {
            int f4 = tid + i * 256;
            int r = f4 >> 4, c = (f4 & 15) * 4;
            *(float4*)&Qs[r][c] = *(const float4*)&qkv[base + (size_t)r * (3 * Ee) + c];
        }
    }

    float m_old = -1e30f, lsum = 0.f;
    float o[8];
    #pragma unroll
    for (int j = 0; j < 8; j++) o[j] = 0.f;

    for (int kt = 0; kt < nkt; kt++) {
        __syncthreads();   // prior tile's sc/Ks/Vs fully consumed
        {
            const size_t kbase = (size_t)(b * Ss + kt * Gg) * (3 * Ee) + Ee + h * HD_;
            #pragma unroll
            for (int i = 0; i < 2; i++) {
                int f4 = tid + i * 256;
                int r = f4 >> 4, c = (f4 & 15) * 4;
                *(float4*)&Ks[r][c] = *(const float4*)&qkv[kbase + (size_t)r * (3 * Ee) + c];
                *(float4*)&Vs[r][c] = *(const float4*)&qkv[kbase + Ee + (size_t)r * (3 * Ee) + c];
            }
        }
        __syncthreads();

        // scores: each thread -> (qrow, koff + {0,8,16,24})
        {
            float a0 = 0.f, a1 = 0.f, a2 = 0.f, a3 = 0.f;
            #pragma unroll
            for (int d4 = 0; d4 < 64; d4 += 4) {
                float4 qv = *(const float4*)&Qs[qrow][d4];
                float4 k0v = *(const float4*)&Ks[koff][d4];
                float4 k1v = *(const float4*)&Ks[koff + 8][d4];
                float4 k2v = *(const float4*)&Ks[koff + 16][d4];
                float4 k3v = *(const float4*)&Ks[koff + 24][d4];
                a0 += qv.x * k0v.x + qv.y * k0v.y + qv.z * k0v.z + qv.w * k0v.w;
                a1 += qv.x * k1v.x + qv.y * k1v.y + qv.z * k1v.z + qv.w * k1v.w;
                a2 += qv.x * k2v.x + qv.y * k2v.y + qv.z * k2v.z + qv.w * k2v.w;
                a3 += qv.x * k3v.x + qv.y * k3v.y + qv.z * k3v.z + qv.w * k3v.w;
            }
            sc[qrow][koff]      = a0 * 0.125f;
            sc[qrow][koff + 8]  = a1 * 0.125f;
            sc[qrow][koff + 16] = a2 * 0.125f;
            sc[qrow][koff + 24] = a3 * 0.125f;
        }
        __syncthreads();

        // row stats (one thread per q)
        if (tid < 32) {
            float mt = -1e30f;
            #pragma unroll
            for (int k = 0; k < 32; k++) mt = fmaxf(mt, sc[tid][k]);
            float mn = fmaxf(m_old, mt);
            float c  = __expf(m_old - mn);
            mrow[tid] = mn; corr_s[tid] = c;
            m_old = mn;
            lsum *= c;
        }
        __syncthreads();

        // p = exp(sc - m)
        {
            float mq = mrow[qrow];
            #pragma unroll
            for (int kk = 0; kk < 4; kk++) {
                int k = koff + kk * 8;
                sc[qrow][k] = __expf(sc[qrow][k] - mq);
            }
        }
        __syncthreads();

        // l update (runs concurrently with PV; both only read sc)
        if (tid < 32) {
            float s = 0.f;
            #pragma unroll
            for (int k = 0; k < 32; k++) s += sc[tid][k];
            lsum += s;
        }

        // PV accumulate
        {
            float c = corr_s[qrow];
            #pragma unroll
            for (int j = 0; j < 8; j++) o[j] *= c;
            #pragma unroll 4
            for (int k = 0; k < 32; k++) {
                float p = sc[qrow][k];
                float4 v0 = *(const float4*)&Vs[k][dbase];
                float4 v1 = *(const float4*)&Vs[k][dbase + 4];
                o[0] += p * v0.x; o[1] += p * v0.y; o[2] += p * v0.z; o[3] += p * v0.w;
                o[4] += p * v1.x; o[5] += p * v1.y; o[6] += p * v1.z; o[7] += p * v1.w;
            }
        }
    }
    __syncthreads();
    if (tid < 32) lrow[tid] = lsum;
    __syncthreads();
    {
        float inv = 1.f / lrow[qrow];
        size_t orow = (size_t)(b * Ss + q0 + qrow) * Ee + h * HD_ + dbase;
        float4 r0 = make_float4(o[0] * inv, o[1] * inv, o[2] * inv, o[3] * inv);
        float4 r1 = make_float4(o[4] * inv, o[5] * inv, o[6] * inv, o[7] * inv);
        *(float4*)&out[orow]     = r0;
        *(float4*)&out[orow + 4] = r1;
    }
}

// ---------------- host orchestration -----------------------------------------
extern "C" void kernel_launch(void* const* d_in, const int* in_sizes, int n_in,
                              void* d_out, int out_size) {
    const float* x      = (const float*)d_in[0];
    const int*   date   = (const int*)  d_in[1];
    const float* wpe    = (const float*)d_in[2];
    const float* ln1_w  = (const float*)d_in[3];
    const float* ln1_b  = (const float*)d_in[4];
    const float* in_w   = (const float*)d_in[5];
    const float* in_b   = (const float*)d_in[6];
    const float* out_w  = (const float*)d_in[7];
    const float* out_b  = (const float*)d_in[8];
    const float* ln2_w  = (const float*)d_in[9];
    const float* ln2_b  = (const float*)d_in[10];
    const float* fc_w   = (const float*)d_in[11];
    const float* fc_b   = (const float*)d_in[12];
    const float* proj_w = (const float*)d_in[13];
    const float* proj_b = (const float*)d_in[14];
    const float* lnf_w  = (const float*)d_in[15];
    const float* lnf_b  = (const float*)d_in[16];
    float* out = (float*)d_out;

    float *h, *y, *qkv, *fc;
    cudaGetSymbolAddress((void**)&h,   g_h);
    cudaGetSymbolAddress((void**)&y,   g_y);
    cudaGetSymbolAddress((void**)&qkv, g_qkv);
    cudaGetSymbolAddress((void**)&fc,  g_fc);

    embed_kernel<<<(NR * Ee + 255) / 256, 256>>>(x, date, wpe);

    for (int l = 0; l < Ll; l++) {
        ln_kernel<<<NR, 256>>>(h, y, ln1_w + (size_t)l * Ee, ln1_b + (size_t)l * Ee);
        gemm_tc<0><<<dim3(3 * Ee / 128, NR / 128), 256>>>(
            y, in_w + (size_t)l * 3 * Ee * Ee, in_b + (size_t)l * 3 * Ee, qkv,
            NR, 3 * Ee, Ee);
        attn_flash<<<dim3(Tt, Hh, Bb), 256>>>(qkv, y);
        gemm_tc<2><<<dim3(Ee / 128, NR / 128), 256>>>(
            y, out_w + (size_t)l * Ee * Ee, out_b + (size_t)l * Ee, h,
            NR, Ee, Ee);
        ln_kernel<<<NR, 256>>>(h, y, ln2_w + (size_t)l * Ee, ln2_b + (size_t)l * Ee);
        gemm_tc<1><<<dim3(4 * Ee / 128, NR / 128), 256>>>(
            y, fc_w + (size_t)l * 4 * Ee * Ee, fc_b + (size_t)l * 4 * Ee, fc,
            NR, 4 * Ee, Ee);
        gemm_tc<2><<<dim3(Ee / 128, NR / 128), 256>>>(
            fc, proj_w + (size_t)l * Ee * 4 * Ee, proj_b + (size_t)l * Ee, h,
            NR, Ee, 4 * Ee);
    }

    ln_kernel<<<NR, 256>>>(h, out, lnf_w, lnf_b);
}

// round 5
// speedup vs baseline: 2.5828x; 1.0011x over previous
#include <cuda_runtime.h>
#include <math.h>

#define Bb 8
#define Tt 32
#define Gg 32
#define Ee 768
#define Hh 12
#define Ll 4
#define Ss (Tt*Gg)        // 1024
#define HD_ (Ee/Hh)       // 64
#define NR (Bb*Ss)        // 8192 rows

// ---------------- scratch (device globals; no cudaMalloc allowed) ------------
__device__ float g_h[NR*Ee];
__device__ float g_y[NR*Ee];
__device__ float g_qkv[NR*3*Ee];
__device__ float g_fc[NR*4*Ee];

// ---------------- embed -------------------------------------------------------
__global__ void embed_kernel(const float* __restrict__ x,
                             const int* __restrict__ date,
                             const float* __restrict__ wpe) {
    int idx = blockIdx.x * blockDim.x + threadIdx.x;
    if (idx >= NR * Ee) return;
    int e   = idx % Ee;
    int row = idx / Ee;
    int b   = row / Ss;
    int s   = row % Ss;
    int t   = s / Gg;
    int d   = date[b * Tt + t];
    d = min(max(d, 0), 49);
    g_h[idx] = x[idx] + wpe[d * Ee + e];
}

// ---------------- layernorm ---------------------------------------------------
__global__ void ln_kernel(const float* __restrict__ in, float* __restrict__ out,
                          const float* __restrict__ w, const float* __restrict__ bia) {
    int row = blockIdx.x;
    const float* xr = in + (size_t)row * Ee;
    __shared__ float red[256];
    int tid = threadIdx.x;
    float s = 0.f;
    for (int e = tid; e < Ee; e += 256) s += xr[e];
    red[tid] = s; __syncthreads();
    for (int o = 128; o > 0; o >>= 1) { if (tid < o) red[tid] += red[tid + o]; __syncthreads(); }
    float mean = red[0] / Ee;
    __syncthreads();
    float v = 0.f;
    for (int e = tid; e < Ee; e += 256) { float d = xr[e] - mean; v += d * d; }
    red[tid] = v; __syncthreads();
    for (int o = 128; o > 0; o >>= 1) { if (tid < o) red[tid] += red[tid + o]; __syncthreads(); }
    float rstd = rsqrtf(red[0] / Ee + 1e-5f);
    for (int e = tid; e < Ee; e += 256)
        out[(size_t)row * Ee + e] = (xr[e] - mean) * rstd * w[e] + bia[e];
}

// ---------------- cp.async helpers -------------------------------------------
__device__ __forceinline__ void cp16(void* s, const void* g) {
    unsigned sa = (unsigned)__cvta_generic_to_shared(s);
    asm volatile("cp.async.ca.shared.global [%0], [%1], 16;\n" :: "r"(sa), "l"(g));
}
__device__ __forceinline__ void cp_commit() {
    asm volatile("cp.async.commit_group;\n" ::);
}
template<int N>
__device__ __forceinline__ void cp_wait() {
    asm volatile("cp.async.wait_group %0;\n" :: "n"(N));
}

// ---------------- tf32 tensor-core GEMM, 3-stage cp.async pipeline ----------
// C[m,n] (op)= sum_k A[m,k]*W[n,k] + bias[n]
// BM=128, BN=WN*64, threads = WN*64 (2 x WN warps), warp tile 64x64.
// One __syncthreads per k-tile; 2 k-tiles of loads in flight.
// EPI: 0 = store, 1 = NewGELU(store), 2 = add into C (residual)
template<int WN, int EPI>
__global__ void __launch_bounds__(WN * 64)
gemm_tc(const float* __restrict__ A, const float* __restrict__ W,
        const float* __restrict__ bias, float* __restrict__ C,
        int M, int N, int K) {
    constexpr int BN  = WN * 64;
    constexpr int NTH = WN * 64;
    __shared__ float As[3][128][20];
    __shared__ float Ws[3][BN][20];

    const int m0 = blockIdx.y * 128;
    const int n0 = blockIdx.x * BN;
    const int tid  = threadIdx.x;
    const int lane = tid & 31;
    const int wid  = tid >> 5;
    const int wm = (wid & 1) * 64;
    const int wn = (wid >> 1) * 64;
    const int gr = lane >> 2;
    const int gc = lane & 3;

    const int KT = K / 16;

    float acc[4][8][4];
    #pragma unroll
    for (int tm = 0; tm < 4; tm++)
        #pragma unroll
        for (int tn = 0; tn < 8; tn++)
            #pragma unroll
            for (int i = 0; i < 4; i++) acc[tm][tn][i] = 0.f;

    // loader lambda-ish: stage st loads k-tile kt
    #define LOAD_TILE(st, kt_) do {                                            \
        int k0 = (kt_) * 16;                                                   \
        _Pragma("unroll")                                                      \
        for (int i = tid; i < (128 + BN) * 4; i += NTH) {                      \
            int r = i >> 2, c = (i & 3) * 4;                                   \
            if (r < 128) cp16(&As[st][r][c], &A[(size_t)(m0 + r) * K + k0 + c]); \
            else         cp16(&Ws[st][r - 128][c], &W[(size_t)(n0 + r - 128) * K + k0 + c]); \
        }                                                                      \
    } while (0)

    LOAD_TILE(0, 0); cp_commit();
    LOAD_TILE(1, 1); cp_commit();

    for (int kt = 0; kt < KT; kt++) {
        int buf = kt % 3;
        cp_wait<1>();          // k-tile kt resident
        __syncthreads();       // all warps done with buffer (kt-1)%3 reuse target
        if (kt + 2 < KT) LOAD_TILE((kt + 2) % 3, kt + 2);
        cp_commit();

        #pragma unroll
        for (int kk = 0; kk < 16; kk += 8) {
            unsigned af[4][4], bf[8][2];
            #pragma unroll
            for (int tm = 0; tm < 4; tm++) {
                int mr = wm + tm * 16 + gr;
                af[tm][0] = __float_as_uint(As[buf][mr][kk + gc]);
                af[tm][1] = __float_as_uint(As[buf][mr + 8][kk + gc]);
                af[tm][2] = __float_as_uint(As[buf][mr][kk + gc + 4]);
                af[tm][3] = __float_as_uint(As[buf][mr + 8][kk + gc + 4]);
            }
            #pragma unroll
            for (int tn = 0; tn < 8; tn++) {
                int nr = wn + tn * 8 + gr;
                bf[tn][0] = __float_as_uint(Ws[buf][nr][kk + gc]);
                bf[tn][1] = __float_as_uint(Ws[buf][nr][kk + gc + 4]);
            }
            #pragma unroll
            for (int tm = 0; tm < 4; tm++)
                #pragma unroll
                for (int tn = 0; tn < 8; tn++)
                    asm volatile(
                        "mma.sync.aligned.m16n8k8.row.col.f32.tf32.tf32.f32 "
                        "{%0,%1,%2,%3}, {%4,%5,%6,%7}, {%8,%9}, {%0,%1,%2,%3};"
                        : "+f"(acc[tm][tn][0]), "+f"(acc[tm][tn][1]),
                          "+f"(acc[tm][tn][2]), "+f"(acc[tm][tn][3])
                        : "r"(af[tm][0]), "r"(af[tm][1]),
                          "r"(af[tm][2]), "r"(af[tm][3]),
                          "r"(bf[tn][0]), "r"(bf[tn][1]));
        }
        __syncthreads();       // done reading buf before loader overwrites (stage dist 3)
    }
    #undef LOAD_TILE

    #pragma unroll
    for (int tm = 0; tm < 4; tm++) {
        #pragma unroll
        for (int tn = 0; tn < 8; tn++) {
            int m = m0 + wm + tm * 16 + gr;
            int n = n0 + wn + tn * 8 + gc * 2;
            float b0 = bias[n], b1 = bias[n + 1];
            #pragma unroll
            for (int half = 0; half < 2; half++) {
                int mm = m + half * 8;
                float v0 = acc[tm][tn][half * 2 + 0] + b0;
                float v1 = acc[tm][tn][half * 2 + 1] + b1;
                size_t o = (size_t)mm * N + n;
                if (EPI == 0) {
                    C[o] = v0; C[o + 1] = v1;
                } else if (EPI == 1) {
                    float u0 = v0 + 0.044715f * v0 * v0 * v0;
                    float u1 = v1 + 0.044715f * v1 * v1 * v1;
                    C[o]     = 0.5f * v0 * (1.0f + tanhf(0.7978845608028654f * u0));
                    C[o + 1] = 0.5f * v1 * (1.0f + tanhf(0.7978845608028654f * u1));
                } else {
                    C[o] += v0; C[o + 1] += v1;
                }
            }
        }
    }
}

// ---------------- flash attention: one block per (b, h, 32-query T-block) ----
__global__ void __launch_bounds__(256)
attn_flash(const float* __restrict__ qkv, float* __restrict__ out) {
    const int tq = (Tt - 1) - blockIdx.x;
    const int h = blockIdx.y, b = blockIdx.z;
    const int q0 = tq * Gg;
    const int nkt = tq + 1;
    const int tid = threadIdx.x;

    __shared__ float Qs[32][68], Ks[32][68], Vs[32][68];
    __shared__ float sc[32][33];
    __shared__ float mrow[32], corr_s[32], lrow[32];

    const int qrow  = tid >> 3;
    const int koff  = tid & 7;
    const int dbase = (tid & 7) * 8;

    {
        const size_t base = (size_t)(b * Ss + q0) * (3 * Ee) + h * HD_;
        #pragma unroll
        for (int i = 0; i < 2; i++) {
            int f4 = tid + i * 256;
            int r = f4 >> 4, c = (f4 & 15) * 4;
            *(float4*)&Qs[r][c] = *(const float4*)&qkv[base + (size_t)r * (3 * Ee) + c];
        }
    }

    float m_old = -1e30f, lsum = 0.f;
    float o[8];
    #pragma unroll
    for (int j = 0; j < 8; j++) o[j] = 0.f;

    for (int kt = 0; kt < nkt; kt++) {
        __syncthreads();
        {
            const size_t kbase = (size_t)(b * Ss + kt * Gg) * (3 * Ee) + Ee + h * HD_;
            #pragma unroll
            for (int i = 0; i < 2; i++) {
                int f4 = tid + i * 256;
                int r = f4 >> 4, c = (f4 & 15) * 4;
                *(float4*)&Ks[r][c] = *(const float4*)&qkv[kbase + (size_t)r * (3 * Ee) + c];
                *(float4*)&Vs[r][c] = *(const float4*)&qkv[kbase + Ee + (size_t)r * (3 * Ee) + c];
            }
        }
        __syncthreads();

        {
            float a0 = 0.f, a1 = 0.f, a2 = 0.f, a3 = 0.f;
            #pragma unroll
            for (int d4 = 0; d4 < 64; d4 += 4) {
                float4 qv = *(const float4*)&Qs[qrow][d4];
                float4 k0v = *(const float4*)&Ks[koff][d4];
                float4 k1v = *(const float4*)&Ks[koff + 8][d4];
                float4 k2v = *(const float4*)&Ks[koff + 16][d4];
                float4 k3v = *(const float4*)&Ks[koff + 24][d4];
                a0 += qv.x * k0v.x + qv.y * k0v.y + qv.z * k0v.z + qv.w * k0v.w;
                a1 += qv.x * k1v.x + qv.y * k1v.y + qv.z * k1v.z + qv.w * k1v.w;
                a2 += qv.x * k2v.x + qv.y * k2v.y + qv.z * k2v.z + qv.w * k2v.w;
                a3 += qv.x * k3v.x + qv.y * k3v.y + qv.z * k3v.z + qv.w * k3v.w;
            }
            sc[qrow][koff]      = a0 * 0.125f;
            sc[qrow][koff + 8]  = a1 * 0.125f;
            sc[qrow][koff + 16] = a2 * 0.125f;
            sc[qrow][koff + 24] = a3 * 0.125f;
        }
        __syncthreads();

        if (tid < 32) {
            float mt = -1e30f;
            #pragma unroll
            for (int k = 0; k < 32; k++) mt = fmaxf(mt, sc[tid][k]);
            float mn = fmaxf(m_old, mt);
            float c  = __expf(m_old - mn);
            mrow[tid] = mn; corr_s[tid] = c;
            m_old = mn;
            lsum *= c;
        }
        __syncthreads();

        {
            float mq = mrow[qrow];
            #pragma unroll
            for (int kk = 0; kk < 4; kk++) {
                int k = koff + kk * 8;
                sc[qrow][k] = __expf(sc[qrow][k] - mq);
            }
        }
        __syncthreads();

        if (tid < 32) {
            float s = 0.f;
            #pragma unroll
            for (int k = 0; k < 32; k++) s += sc[tid][k];
            lsum += s;
        }

        {
            float c = corr_s[qrow];
            #pragma unroll
            for (int j = 0; j < 8; j++) o[j] *= c;
            #pragma unroll 4
            for (int k = 0; k < 32; k++) {
                float p = sc[qrow][k];
                float4 v0 = *(const float4*)&Vs[k][dbase];
                float4 v1 = *(const float4*)&Vs[k][dbase + 4];
                o[0] += p * v0.x; o[1] += p * v0.y; o[2] += p * v0.z; o[3] += p * v0.w;
                o[4] += p * v1.x; o[5] += p * v1.y; o[6] += p * v1.z; o[7] += p * v1.w;
            }
        }
    }
    __syncthreads();
    if (tid < 32) lrow[tid] = lsum;
    __syncthreads();
    {
        float inv = 1.f / lrow[qrow];
        size_t orow = (size_t)(b * Ss + q0 + qrow) * Ee + h * HD_ + dbase;
        float4 r0 = make_float4(o[0] * inv, o[1] * inv, o[2] * inv, o[3] * inv);
        float4 r1 = make_float4(o[4] * inv, o[5] * inv, o[6] * inv, o[7] * inv);
        *(float4*)&out[orow]     = r0;
        *(float4*)&out[orow + 4] = r1;
    }
}

// ---------------- host orchestration -----------------------------------------
extern "C" void kernel_launch(void* const* d_in, const int* in_sizes, int n_in,
                              void* d_out, int out_size) {
    const float* x      = (const float*)d_in[0];
    const int*   date   = (const int*)  d_in[1];
    const float* wpe    = (const float*)d_in[2];
    const float* ln1_w  = (const float*)d_in[3];
    const float* ln1_b  = (const float*)d_in[4];
    const float* in_w   = (const float*)d_in[5];
    const float* in_b   = (const float*)d_in[6];
    const float* out_w  = (const float*)d_in[7];
    const float* out_b  = (const float*)d_in[8];
    const float* ln2_w  = (const float*)d_in[9];
    const float* ln2_b  = (const float*)d_in[10];
    const float* fc_w   = (const float*)d_in[11];
    const float* fc_b   = (const float*)d_in[12];
    const float* proj_w = (const float*)d_in[13];
    const float* proj_b = (const float*)d_in[14];
    const float* lnf_w  = (const float*)d_in[15];
    const float* lnf_b  = (const float*)d_in[16];
    float* out = (float*)d_out;

    float *h, *y, *qkv, *fc;
    cudaGetSymbolAddress((void**)&h,   g_h);
    cudaGetSymbolAddress((void**)&y,   g_y);
    cudaGetSymbolAddress((void**)&qkv, g_qkv);
    cudaGetSymbolAddress((void**)&fc,  g_fc);

    embed_kernel<<<(NR * Ee + 255) / 256, 256>>>(x, date, wpe);

    for (int l = 0; l < Ll; l++) {
        ln_kernel<<<NR, 256>>>(h, y, ln1_w + (size_t)l * Ee, ln1_b + (size_t)l * Ee);
        // QKV: [8192 x 2304], wide config (BN=256)
        gemm_tc<4, 0><<<dim3(3 * Ee / 256, NR / 128), 256>>>(
            y, in_w + (size_t)l * 3 * Ee * Ee, in_b + (size_t)l * 3 * Ee, qkv,
            NR, 3 * Ee, Ee);
        attn_flash<<<dim3(Tt, Hh, Bb), 256>>>(qkv, y);
        // out-proj: [8192 x 768], narrow config (BN=128, 128 thr, 2 CTA/SM)
        gemm_tc<2, 2><<<dim3(Ee / 128, NR / 128), 128>>>(
            y, out_w + (size_t)l * Ee * Ee, out_b + (size_t)l * Ee, h,
            NR, Ee, Ee);
        ln_kernel<<<NR, 256>>>(h, y, ln2_w + (size_t)l * Ee, ln2_b + (size_t)l * Ee);
        // fc: [8192 x 3072], wide
        gemm_tc<4, 1><<<dim3(4 * Ee / 256, NR / 128), 256>>>(
            y, fc_w + (size_t)l * 4 * Ee * Ee, fc_b + (size_t)l * 4 * Ee, fc,
            NR, 4 * Ee, Ee);
        // proj: [8192 x 768], K=3072, narrow
        gemm_tc<2, 2><<<dim3(Ee / 128, NR / 128), 128>>>(
            fc, proj_w + (size_t)l * Ee * 4 * Ee, proj_b + (size_t)l * Ee, h,
            NR, Ee, 4 * Ee);
    }

    ln_kernel<<<NR, 256>>>(h, out, lnf_w, lnf_b);
}

// round 6
// speedup vs baseline: 4.7124x; 1.8246x over previous
#include <cuda_runtime.h>
#include <cuda_fp16.h>
#include <math.h>

#define Bb 8
#define Tt 32
#define Gg 32
#define Ee 768
#define Hh 12
#define Ll 4
#define Ss (Tt*Gg)        // 1024
#define HD_ (Ee/Hh)       // 64
#define NR (Bb*Ss)        // 8192 rows

// weight (half) buffer offsets
#define W_IN_CNT   (Ll*3*Ee*Ee)   // 7077888
#define W_OUT_CNT  (Ll*Ee*Ee)     // 2359296
#define W_FC_CNT   (Ll*4*Ee*Ee)   // 9437184
#define W_PROJ_CNT (Ll*Ee*4*Ee)   // 9437184

// ---------------- scratch (device globals; no cudaMalloc allowed) ------------
__device__ float  g_h[NR*Ee];             // residual stream (fp32)
__device__ __half g_y[NR*Ee];             // ln / attn output (fp16)
__device__ __half g_qkv[NR*3*Ee];         // qkv (fp16)
__device__ __half g_fc[NR*4*Ee];          // mlp hidden (fp16)
__device__ __half g_wh[W_IN_CNT + W_OUT_CNT + W_FC_CNT + W_PROJ_CNT];

// ---------------- fp32 -> fp16 weight conversion ------------------------------
__global__ void f2h4_kernel(const float* __restrict__ in, __half* __restrict__ out, int n4) {
    int i = blockIdx.x * blockDim.x + threadIdx.x;
    if (i >= n4) return;
    float4 v = ((const float4*)in)[i];
    __half2 a = __floats2half2_rn(v.x, v.y);
    __half2 b = __floats2half2_rn(v.z, v.w);
    ((__half2*)out)[i * 2]     = a;
    ((__half2*)out)[i * 2 + 1] = b;
}

// ---------------- embed -------------------------------------------------------
__global__ void embed_kernel(const float* __restrict__ x,
                             const int* __restrict__ date,
                             const float* __restrict__ wpe) {
    int idx = blockIdx.x * blockDim.x + threadIdx.x;
    if (idx >= NR * Ee) return;
    int e   = idx % Ee;
    int row = idx / Ee;
    int b   = row / Ss;
    int s   = row % Ss;
    int t   = s / Gg;
    int d   = date[b * Tt + t];
    d = min(max(d, 0), 49);
    g_h[idx] = x[idx] + wpe[d * Ee + e];
}

// ---------------- layernorm (templated output type) ---------------------------
template<typename OT>
__global__ void ln_kernel(const float* __restrict__ in, OT* __restrict__ out,
                          const float* __restrict__ w, const float* __restrict__ bia) {
    int row = blockIdx.x;
    const float* xr = in + (size_t)row * Ee;
    __shared__ float red[256];
    int tid = threadIdx.x;
    float s = 0.f;
    for (int e = tid; e < Ee; e += 256) s += xr[e];
    red[tid] = s; __syncthreads();
    for (int o = 128; o > 0; o >>= 1) { if (tid < o) red[tid] += red[tid + o]; __syncthreads(); }
    float mean = red[0] / Ee;
    __syncthreads();
    float v = 0.f;
    for (int e = tid; e < Ee; e += 256) { float d = xr[e] - mean; v += d * d; }
    red[tid] = v; __syncthreads();
    for (int o = 128; o > 0; o >>= 1) { if (tid < o) red[tid] += red[tid + o]; __syncthreads(); }
    float rstd = rsqrtf(red[0] / Ee + 1e-5f);
    for (int e = tid; e < Ee; e += 256)
        out[(size_t)row * Ee + e] = (OT)((xr[e] - mean) * rstd * w[e] + bia[e]);
}

// ---------------- cp.async helpers -------------------------------------------
__device__ __forceinline__ void cp16(void* s, const void* g) {
    unsigned sa = (unsigned)__cvta_generic_to_shared(s);
    asm volatile("cp.async.ca.shared.global [%0], [%1], 16;\n" :: "r"(sa), "l"(g));
}
__device__ __forceinline__ void cp_commit() {
    asm volatile("cp.async.commit_group;\n" ::);
}
template<int N>
__device__ __forceinline__ void cp_wait() {
    asm volatile("cp.async.wait_group %0;\n" :: "n"(N));
}

// ---------------- fp16 tensor-core GEMM, 3-stage cp.async pipeline -----------
// C[m,n] (op)= sum_k A[m,k]*W[n,k] + bias[n];  A,W fp16; acc fp32.
// BM=128, BN=WN*64, threads = WN*64 (2 x WN warps), warp tile 64x64, BK=32.
// EPI: 0 = store half, 1 = NewGELU -> half, 2 = add fp32 into C (residual)
template<int WN, int EPI>
__global__ void __launch_bounds__(WN * 64)
gemm_h(const __half* __restrict__ A, const __half* __restrict__ W,
       const float* __restrict__ bias, void* __restrict__ Cv,
       int M, int N, int K) {
    constexpr int BN  = WN * 64;
    constexpr int NTH = WN * 64;
    __shared__ __half As[3][128][40];   // 32 halfs + 8 pad (80B stride)
    __shared__ __half Ws[3][BN][40];

    const int m0 = blockIdx.y * 128;
    const int n0 = blockIdx.x * BN;
    const int tid  = threadIdx.x;
    const int lane = tid & 31;
    const int wid  = tid >> 5;
    const int wm = (wid & 1) * 64;
    const int wn = (wid >> 1) * 64;
    const int gr = lane >> 2;
    const int gc = lane & 3;

    const int KT = K / 32;

    float acc[4][8][4];
    #pragma unroll
    for (int tm = 0; tm < 4; tm++)
        #pragma unroll
        for (int tn = 0; tn < 8; tn++)
            #pragma unroll
            for (int i = 0; i < 4; i++) acc[tm][tn][i] = 0.f;

    #define LOAD_TILE(st, kt_) do {                                              \
        int k0 = (kt_) * 32;                                                     \
        _Pragma("unroll")                                                        \
        for (int i = tid; i < (128 + BN) * 4; i += NTH) {                        \
            int r = i >> 2, c = (i & 3) * 8;                                     \
            if (r < 128) cp16(&As[st][r][c], &A[(size_t)(m0 + r) * K + k0 + c]); \
            else         cp16(&Ws[st][r - 128][c], &W[(size_t)(n0 + r - 128) * K + k0 + c]); \
        }                                                                        \
    } while (0)

    LOAD_TILE(0, 0); cp_commit();
    LOAD_TILE(1, 1); cp_commit();

    for (int kt = 0; kt < KT; kt++) {
        int buf = kt % 3;
        cp_wait<1>();
        __syncthreads();
        if (kt + 2 < KT) LOAD_TILE((kt + 2) % 3, kt + 2);
        cp_commit();

        #pragma unroll
        for (int kk = 0; kk < 32; kk += 16) {
            unsigned af[4][4], bf[8][2];
            #pragma unroll
            for (int tm = 0; tm < 4; tm++) {
                int mr = wm + tm * 16 + gr;
                af[tm][0] = *(const unsigned*)&As[buf][mr][kk + gc * 2];
                af[tm][1] = *(const unsigned*)&As[buf][mr + 8][kk + gc * 2];
                af[tm][2] = *(const unsigned*)&As[buf][mr][kk + gc * 2 + 8];
                af[tm][3] = *(const unsigned*)&As[buf][mr + 8][kk + gc * 2 + 8];
            }
            #pragma unroll
            for (int tn = 0; tn < 8; tn++) {
                int nr = wn + tn * 8 + gr;
                bf[tn][0] = *(const unsigned*)&Ws[buf][nr][kk + gc * 2];
                bf[tn][1] = *(const unsigned*)&Ws[buf][nr][kk + gc * 2 + 8];
            }
            #pragma unroll
            for (int tm = 0; tm < 4; tm++)
                #pragma unroll
                for (int tn = 0; tn < 8; tn++)
                    asm volatile(
                        "mma.sync.aligned.m16n8k16.row.col.f32.f16.f16.f32 "
                        "{%0,%1,%2,%3}, {%4,%5,%6,%7}, {%8,%9}, {%0,%1,%2,%3};"
                        : "+f"(acc[tm][tn][0]), "+f"(acc[tm][tn][1]),
                          "+f"(acc[tm][tn][2]), "+f"(acc[tm][tn][3])
                        : "r"(af[tm][0]), "r"(af[tm][1]),
                          "r"(af[tm][2]), "r"(af[tm][3]),
                          "r"(bf[tn][0]), "r"(bf[tn][1]));
        }
        __syncthreads();
    }
    #undef LOAD_TILE

    #pragma unroll
    for (int tm = 0; tm < 4; tm++) {
        #pragma unroll
        for (int tn = 0; tn < 8; tn++) {
            int m = m0 + wm + tm * 16 + gr;
            int n = n0 + wn + tn * 8 + gc * 2;
            float b0 = bias[n], b1 = bias[n + 1];
            #pragma unroll
            for (int half_ = 0; half_ < 2; half_++) {
                int mm = m + half_ * 8;
                float v0 = acc[tm][tn][half_ * 2 + 0] + b0;
                float v1 = acc[tm][tn][half_ * 2 + 1] + b1;
                size_t o = (size_t)mm * N + n;
                if (EPI == 0) {
                    *(__half2*)((__half*)Cv + o) = __floats2half2_rn(v0, v1);
                } else if (EPI == 1) {
                    float u0 = v0 + 0.044715f * v0 * v0 * v0;
                    float u1 = v1 + 0.044715f * v1 * v1 * v1;
                    float g0 = 0.5f * v0 * (1.0f + tanhf(0.7978845608028654f * u0));
                    float g1 = 0.5f * v1 * (1.0f + tanhf(0.7978845608028654f * u1));
                    *(__half2*)((__half*)Cv + o) = __floats2half2_rn(g0, g1);
                } else {
                    float* C = (float*)Cv;
                    C[o] += v0; C[o + 1] += v1;
                }
            }
        }
    }
}

// ---------------- flash attention (fp16 smem, fp32 math) ---------------------
__device__ __forceinline__ void h8f(const uint4 u, float f[8]) {
    float2 t;
    t = __half22float2(*(const __half2*)&u.x); f[0] = t.x; f[1] = t.y;
    t = __half22float2(*(const __half2*)&u.y); f[2] = t.x; f[3] = t.y;
    t = __half22float2(*(const __half2*)&u.z); f[4] = t.x; f[5] = t.y;
    t = __half22float2(*(const __half2*)&u.w); f[6] = t.x; f[7] = t.y;
}

__global__ void __launch_bounds__(256)
attn_flash(const __half* __restrict__ qkv, __half* __restrict__ out) {
    const int tq = (Tt - 1) - blockIdx.x;
    const int h = blockIdx.y, b = blockIdx.z;
    const int q0 = tq * Gg;
    const int nkt = tq + 1;
    const int tid = threadIdx.x;

    __shared__ __half Qs[32][72], Ks[32][72], Vs[32][72];
    __shared__ float sc[32][33];
    __shared__ float mrow[32], corr_s[32], lrow[32];

    const int qrow  = tid >> 3;
    const int koff  = tid & 7;
    const int dbase = (tid & 7) * 8;

    const int lr = tid >> 3;           // load row 0..31
    const int lc = (tid & 7) * 8;      // load col (halfs)

    {
        const size_t base = (size_t)(b * Ss + q0) * (3 * Ee) + h * HD_;
        *(uint4*)&Qs[lr][lc] = *(const uint4*)&qkv[base + (size_t)lr * (3 * Ee) + lc];
    }

    float m_old = -1e30f, lsum = 0.f;
    float o[8];
    #pragma unroll
    for (int j = 0; j < 8; j++) o[j] = 0.f;

    for (int kt = 0; kt < nkt; kt++) {
        __syncthreads();
        {
            const size_t kbase = (size_t)(b * Ss + kt * Gg) * (3 * Ee) + Ee + h * HD_;
            *(uint4*)&Ks[lr][lc] = *(const uint4*)&qkv[kbase + (size_t)lr * (3 * Ee) + lc];
            *(uint4*)&Vs[lr][lc] = *(const uint4*)&qkv[kbase + Ee + (size_t)lr * (3 * Ee) + lc];
        }
        __syncthreads();

        // scores: thread -> (qrow, koff + {0,8,16,24})
        {
            float a0 = 0.f, a1 = 0.f, a2 = 0.f, a3 = 0.f;
            #pragma unroll
            for (int c = 0; c < 64; c += 8) {
                float qf[8], k0f[8], k1f[8], k2f[8], k3f[8];
                h8f(*(const uint4*)&Qs[qrow][c], qf);
                h8f(*(const uint4*)&Ks[koff][c], k0f);
                h8f(*(const uint4*)&Ks[koff + 8][c], k1f);
                h8f(*(const uint4*)&Ks[koff + 16][c], k2f);
                h8f(*(const uint4*)&Ks[koff + 24][c], k3f);
                #pragma unroll
                for (int j = 0; j < 8; j++) {
                    a0 += qf[j] * k0f[j];
                    a1 += qf[j] * k1f[j];
                    a2 += qf[j] * k2f[j];
                    a3 += qf[j] * k3f[j];
                }
            }
            sc[qrow][koff]      = a0 * 0.125f;
            sc[qrow][koff + 8]  = a1 * 0.125f;
            sc[qrow][koff + 16] = a2 * 0.125f;
            sc[qrow][koff + 24] = a3 * 0.125f;
        }
        __syncthreads();

        if (tid < 32) {
            float mt = -1e30f;
            #pragma unroll
            for (int k = 0; k < 32; k++) mt = fmaxf(mt, sc[tid][k]);
            float mn = fmaxf(m_old, mt);
            float c  = __expf(m_old - mn);
            mrow[tid] = mn; corr_s[tid] = c;
            m_old = mn;
            lsum *= c;
        }
        __syncthreads();

        {
            float mq = mrow[qrow];
            #pragma unroll
            for (int kk = 0; kk < 4; kk++) {
                int k = koff + kk * 8;
                sc[qrow][k] = __expf(sc[qrow][k] - mq);
            }
        }
        __syncthreads();

        if (tid < 32) {
            float s = 0.f;
            #pragma unroll
            for (int k = 0; k < 32; k++) s += sc[tid][k];
            lsum += s;
        }

        {
            float c = corr_s[qrow];
            #pragma unroll
            for (int j = 0; j < 8; j++) o[j] *= c;
            #pragma unroll 4
            for (int k = 0; k < 32; k++) {
                float p = sc[qrow][k];
                float vf[8];
                h8f(*(const uint4*)&Vs[k][dbase], vf);
                #pragma unroll
                for (int j = 0; j < 8; j++) o[j] += p * vf[j];
            }
        }
    }
    __syncthreads();
    if (tid < 32) lrow[tid] = lsum;
    __syncthreads();
    {
        float inv = 1.f / lrow[qrow];
        size_t orow = (size_t)(b * Ss + q0 + qrow) * Ee + h * HD_ + dbase;
        __half2 r0 = __floats2half2_rn(o[0] * inv, o[1] * inv);
        __half2 r1 = __floats2half2_rn(o[2] * inv, o[3] * inv);
        __half2 r2 = __floats2half2_rn(o[4] * inv, o[5] * inv);
        __half2 r3 = __floats2half2_rn(o[6] * inv, o[7] * inv);
        uint4 pack;
        pack.x = *(unsigned*)&r0; pack.y = *(unsigned*)&r1;
        pack.z = *(unsigned*)&r2; pack.w = *(unsigned*)&r3;
        *(uint4*)&out[orow] = pack;
    }
}

// ---------------- host orchestration -----------------------------------------
extern "C" void kernel_launch(void* const* d_in, const int* in_sizes, int n_in,
                              void* d_out, int out_size) {
    const float* x      = (const float*)d_in[0];
    const int*   date   = (const int*)  d_in[1];
    const float* wpe    = (const float*)d_in[2];
    const float* ln1_w  = (const float*)d_in[3];
    const float* ln1_b  = (const float*)d_in[4];
    const float* in_w   = (const float*)d_in[5];
    const float* in_b   = (const float*)d_in[6];
    const float* out_w  = (const float*)d_in[7];
    const float* out_b  = (const float*)d_in[8];
    const float* ln2_w  = (const float*)d_in[9];
    const float* ln2_b  = (const float*)d_in[10];
    const float* fc_w   = (const float*)d_in[11];
    const float* fc_b   = (const float*)d_in[12];
    const float* proj_w = (const float*)d_in[13];
    const float* proj_b = (const float*)d_in[14];
    const float* lnf_w  = (const float*)d_in[15];
    const float* lnf_b  = (const float*)d_in[16];
    float* out = (float*)d_out;

    float  *h;
    __half *y, *qkv, *fc, *wh;
    cudaGetSymbolAddress((void**)&h,   g_h);
    cudaGetSymbolAddress((void**)&y,   g_y);
    cudaGetSymbolAddress((void**)&qkv, g_qkv);
    cudaGetSymbolAddress((void**)&fc,  g_fc);
    cudaGetSymbolAddress((void**)&wh,  g_wh);

    __half* in_wh   = wh;
    __half* out_wh  = wh + W_IN_CNT;
    __half* fc_wh   = wh + W_IN_CNT + W_OUT_CNT;
    __half* proj_wh = wh + W_IN_CNT + W_OUT_CNT + W_FC_CNT;

    // weight conversion (fp32 -> fp16)
    f2h4_kernel<<<(W_IN_CNT / 4 + 255) / 256, 256>>>(in_w, in_wh, W_IN_CNT / 4);
    f2h4_kernel<<<(W_OUT_CNT / 4 + 255) / 256, 256>>>(out_w, out_wh, W_OUT_CNT / 4);
    f2h4_kernel<<<(W_FC_CNT / 4 + 255) / 256, 256>>>(fc_w, fc_wh, W_FC_CNT / 4);
    f2h4_kernel<<<(W_PROJ_CNT / 4 + 255) / 256, 256>>>(proj_w, proj_wh, W_PROJ_CNT / 4);

    embed_kernel<<<(NR * Ee + 255) / 256, 256>>>(x, date, wpe);

    for (int l = 0; l < Ll; l++) {
        ln_kernel<__half><<<NR, 256>>>(h, y, ln1_w + (size_t)l * Ee, ln1_b + (size_t)l * Ee);
        // QKV: [8192 x 2304], wide (BN=256)
        gemm_h<4, 0><<<dim3(3 * Ee / 256, NR / 128), 256>>>(
            y, in_wh + (size_t)l * 3 * Ee * Ee, in_b + (size_t)l * 3 * Ee, qkv,
            NR, 3 * Ee, Ee);
        attn_flash<<<dim3(Tt, Hh, Bb), 256>>>(qkv, y);
        // out-proj: [8192 x 768], narrow (BN=128, 128 thr)
        gemm_h<2, 2><<<dim3(Ee / 128, NR / 128), 128>>>(
            y, out_wh + (size_t)l * Ee * Ee, out_b + (size_t)l * Ee, h,
            NR, Ee, Ee);
        ln_kernel<__half><<<NR, 256>>>(h, y, ln2_w + (size_t)l * Ee, ln2_b + (size_t)l * Ee);
        // fc: [8192 x 3072], wide
        gemm_h<4, 1><<<dim3(4 * Ee / 256, NR / 128), 256>>>(
            y, fc_wh + (size_t)l * 4 * Ee * Ee, fc_b + (size_t)l * 4 * Ee, fc,
            NR, 4 * Ee, Ee);
        // proj: [8192 x 768], K=3072, narrow
        gemm_h<2, 2><<<dim3(Ee / 128, NR / 128), 128>>>(
            fc, proj_wh + (size_t)l * Ee * 4 * Ee, proj_b + (size_t)l * Ee, h,
            NR, Ee, 4 * Ee);
    }

    ln_kernel<float><<<NR, 256>>>(h, out, lnf_w, lnf_b);
}

// round 10
// speedup vs baseline: 8.4247x; 1.7878x over previous
#include <cuda_runtime.h>
#include <cuda_fp16.h>
#include <math.h>

#define Bb 8
#define Tt 32
#define Gg 32
#define Ee 768
#define Hh 12
#define Ll 4
#define Ss (Tt*Gg)        // 1024
#define HD_ (Ee/Hh)       // 64
#define NR (Bb*Ss)        // 8192 rows

// weight (half) buffer offsets
#define W_IN_CNT   (Ll*3*Ee*Ee)
#define W_OUT_CNT  (Ll*Ee*Ee)
#define W_FC_CNT   (Ll*4*Ee*Ee)
#define W_PROJ_CNT (Ll*Ee*4*Ee)

// ---------------- scratch (device globals; no cudaMalloc allowed) ------------
__device__ float  g_h[NR*Ee];             // residual stream (fp32)
__device__ __half g_y[NR*Ee];             // ln / attn output (fp16)
__device__ __half g_qkv[NR*3*Ee];         // qkv (fp16)
__device__ __half g_fc[NR*4*Ee];          // mlp hidden (fp16)
__device__ __half g_wh[W_IN_CNT + W_OUT_CNT + W_FC_CNT + W_PROJ_CNT];

// ---------------- fp32 -> fp16 weight conversion ------------------------------
__global__ void f2h4_kernel(const float* __restrict__ in, __half* __restrict__ out, int n4) {
    int i = blockIdx.x * blockDim.x + threadIdx.x;
    if (i >= n4) return;
    float4 v = ((const float4*)in)[i];
    __half2 a = __floats2half2_rn(v.x, v.y);
    __half2 b = __floats2half2_rn(v.z, v.w);
    ((__half2*)out)[i * 2]     = a;
    ((__half2*)out)[i * 2 + 1] = b;
}

// ---------------- embed -------------------------------------------------------
__global__ void embed_kernel(const float* __restrict__ x,
                             const int* __restrict__ date,
                             const float* __restrict__ wpe) {
    int idx = blockIdx.x * blockDim.x + threadIdx.x;
    if (idx >= NR * Ee) return;
    int e   = idx % Ee;
    int row = idx / Ee;
    int b   = row / Ss;
    int s   = row % Ss;
    int t   = s / Gg;
    int d   = date[b * Tt + t];
    d = min(max(d, 0), 49);
    g_h[idx] = x[idx] + wpe[d * Ee + e];
}

// ---------------- layernorm (templated output type) ---------------------------
template<typename OT>
__global__ void ln_kernel(const float* __restrict__ in, OT* __restrict__ out,
                          const float* __restrict__ w, const float* __restrict__ bia) {
    int row = blockIdx.x;
    const float* xr = in + (size_t)row * Ee;
    __shared__ float red[256];
    int tid = threadIdx.x;
    float s = 0.f;
    for (int e = tid; e < Ee; e += 256) s += xr[e];
    red[tid] = s; __syncthreads();
    for (int o = 128; o > 0; o >>= 1) { if (tid < o) red[tid] += red[tid + o]; __syncthreads(); }
    float mean = red[0] / Ee;
    __syncthreads();
    float v = 0.f;
    for (int e = tid; e < Ee; e += 256) { float d = xr[e] - mean; v += d * d; }
    red[tid] = v; __syncthreads();
    for (int o = 128; o > 0; o >>= 1) { if (tid < o) red[tid] += red[tid + o]; __syncthreads(); }
    float rstd = rsqrtf(red[0] / Ee + 1e-5f);
    for (int e = tid; e < Ee; e += 256)
        out[(size_t)row * Ee + e] = (OT)((xr[e] - mean) * rstd * w[e] + bia[e]);
}

// ---------------- cp.async helpers -------------------------------------------
__device__ __forceinline__ void cp16(void* s, const void* g) {
    unsigned sa = (unsigned)__cvta_generic_to_shared(s);
    asm volatile("cp.async.ca.shared.global [%0], [%1], 16;\n" :: "r"(sa), "l"(g));
}
__device__ __forceinline__ void cp_commit() {
    asm volatile("cp.async.commit_group;\n" ::);
}
template<int N>
__device__ __forceinline__ void cp_wait() {
    asm volatile("cp.async.wait_group %0;\n" :: "n"(N));
}

// ---------------- mma / ldmatrix helpers --------------------------------------
__device__ __forceinline__ void mma16816(float c[4], const unsigned a[4],
                                         unsigned b0, unsigned b1) {
    asm volatile("mma.sync.aligned.m16n8k16.row.col.f32.f16.f16.f32 "
                 "{%0,%1,%2,%3}, {%4,%5,%6,%7}, {%8,%9}, {%0,%1,%2,%3};"
                 : "+f"(c[0]), "+f"(c[1]), "+f"(c[2]), "+f"(c[3])
                 : "r"(a[0]), "r"(a[1]), "r"(a[2]), "r"(a[3]), "r"(b0), "r"(b1));
}
__device__ __forceinline__ void ldsm_x2_t(unsigned &r0, unsigned &r1, const void* p) {
    unsigned a = (unsigned)__cvta_generic_to_shared(p);
    asm volatile("ldmatrix.sync.aligned.m8n8.x2.trans.shared.b16 {%0,%1}, [%2];"
                 : "=r"(r0), "=r"(r1) : "r"(a));
}

// ---------------- fp16 tensor-core GEMM, 3-stage cp.async pipeline -----------
template<int WN, int EPI>
__global__ void __launch_bounds__(WN * 64)
gemm_h(const __half* __restrict__ A, const __half* __restrict__ W,
       const float* __restrict__ bias, void* __restrict__ Cv,
       int M, int N, int K) {
    constexpr int BN  = WN * 64;
    constexpr int NTH = WN * 64;
    __shared__ __half As[3][128][40];
    __shared__ __half Ws[3][BN][40];

    const int m0 = blockIdx.y * 128;
    const int n0 = blockIdx.x * BN;
    const int tid  = threadIdx.x;
    const int lane = tid & 31;
    const int wid  = tid >> 5;
    const int wm = (wid & 1) * 64;
    const int wn = (wid >> 1) * 64;
    const int gr = lane >> 2;
    const int gc = lane & 3;

    const int KT = K / 32;

    float acc[4][8][4];
    #pragma unroll
    for (int tm = 0; tm < 4; tm++)
        #pragma unroll
        for (int tn = 0; tn < 8; tn++)
            #pragma unroll
            for (int i = 0; i < 4; i++) acc[tm][tn][i] = 0.f;

    #define LOAD_TILE(st, kt_) do {                                              \
        int k0 = (kt_) * 32;                                                     \
        _Pragma("unroll")                                                        \
        for (int i = tid; i < (128 + BN) * 4; i += NTH) {                        \
            int r = i >> 2, c = (i & 3) * 8;                                     \
            if (r < 128) cp16(&As[st][r][c], &A[(size_t)(m0 + r) * K + k0 + c]); \
            else         cp16(&Ws[st][r - 128][c], &W[(size_t)(n0 + r - 128) * K + k0 + c]); \
        }                                                                        \
    } while (0)

    LOAD_TILE(0, 0); cp_commit();
    LOAD_TILE(1, 1); cp_commit();

    for (int kt = 0; kt < KT; kt++) {
        int buf = kt % 3;
        cp_wait<1>();
        __syncthreads();
        if (kt + 2 < KT) LOAD_TILE((kt + 2) % 3, kt + 2);
        cp_commit();

        #pragma unroll
        for (int kk = 0; kk < 32; kk += 16) {
            unsigned af[4][4], bf[8][2];
            #pragma unroll
            for (int tm = 0; tm < 4; tm++) {
                int mr = wm + tm * 16 + gr;
                af[tm][0] = *(const unsigned*)&As[buf][mr][kk + gc * 2];
                af[tm][1] = *(const unsigned*)&As[buf][mr + 8][kk + gc * 2];
                af[tm][2] = *(const unsigned*)&As[buf][mr][kk + gc * 2 + 8];
                af[tm][3] = *(const unsigned*)&As[buf][mr + 8][kk + gc * 2 + 8];
            }
            #pragma unroll
            for (int tn = 0; tn < 8; tn++) {
                int nr = wn + tn * 8 + gr;
                bf[tn][0] = *(const unsigned*)&Ws[buf][nr][kk + gc * 2];
                bf[tn][1] = *(const unsigned*)&Ws[buf][nr][kk + gc * 2 + 8];
            }
            #pragma unroll
            for (int tm = 0; tm < 4; tm++)
                #pragma unroll
                for (int tn = 0; tn < 8; tn++)
                    mma16816(acc[tm][tn], af[tm], bf[tn][0], bf[tn][1]);
        }
        __syncthreads();
    }
    #undef LOAD_TILE

    #pragma unroll
    for (int tm = 0; tm < 4; tm++) {
        #pragma unroll
        for (int tn = 0; tn < 8; tn++) {
            int m = m0 + wm + tm * 16 + gr;
            int n = n0 + wn + tn * 8 + gc * 2;
            float b0 = bias[n], b1 = bias[n + 1];
            #pragma unroll
            for (int half_ = 0; half_ < 2; half_++) {
                int mm = m + half_ * 8;
                float v0 = acc[tm][tn][half_ * 2 + 0] + b0;
                float v1 = acc[tm][tn][half_ * 2 + 1] + b1;
                size_t o = (size_t)mm * N + n;
                if (EPI == 0) {
                    *(__half2*)((__half*)Cv + o) = __floats2half2_rn(v0, v1);
                } else if (EPI == 1) {
                    float u0 = v0 + 0.044715f * v0 * v0 * v0;
                    float u1 = v1 + 0.044715f * v1 * v1 * v1;
                    float g0 = 0.5f * v0 * (1.0f + tanhf(0.7978845608028654f * u0));
                    float g1 = 0.5f * v1 * (1.0f + tanhf(0.7978845608028654f * u1));
                    *(__half2*)((__half*)Cv + o) = __floats2half2_rn(g0, g1);
                } else {
                    float* C = (float*)Cv;
                    C[o] += v0; C[o + 1] += v1;
                }
            }
        }
    }
}

// ---------------- tensor-core flash attention ---------------------------------
// One block per (b, h, 32-query T-block); 2 warps, each owns 16 q-rows.
// Q lives in registers as mma A-fragments; K via LDS.32 B-fragments;
// V via ldmatrix.x2.trans; P converted in-register (C-layout -> A-layout).
__global__ void __launch_bounds__(64)
attn_mma(const __half* __restrict__ qkv, __half* __restrict__ out) {
    const int tq = (Tt - 1) - blockIdx.x;    // heavy tiles first
    const int h = blockIdx.y, b = blockIdx.z;
    const int q0 = tq * Gg;
    const int nkt = tq + 1;
    const int tid  = threadIdx.x;
    const int lane = tid & 31;
    const int warp = tid >> 5;
    const int gr = lane >> 2, gc = lane & 3;
    const int mw = warp * 16;

    __shared__ __half Qs[32][72];
    __shared__ __half Ks[2][32][72];
    __shared__ __half Vs[2][32][72];

    const size_t stride = 3 * Ee;
    const size_t qbase = (size_t)(b * Ss + q0) * stride + h * HD_;

    // prologue: async K/V tile 0
    {
        size_t kb = (size_t)(b * Ss) * stride + Ee + h * HD_;
        #pragma unroll
        for (int i = 0; i < 4; i++) {
            int t = tid + i * 64; int r = t >> 3, c = (t & 7) * 8;
            cp16(&Ks[0][r][c], &qkv[kb + (size_t)r * stride + c]);
            cp16(&Vs[0][r][c], &qkv[kb + Ee + (size_t)r * stride + c]);
        }
        cp_commit();
    }
    // Q tile direct
    #pragma unroll
    for (int i = 0; i < 4; i++) {
        int t = tid + i * 64; int r = t >> 3, c = (t & 7) * 8;
        *(uint4*)&Qs[r][c] = *(const uint4*)&qkv[qbase + (size_t)r * stride + c];
    }
    __syncthreads();

    // Q fragments (held for entire kernel)
    unsigned qa[4][4];
    #pragma unroll
    for (int kc = 0; kc < 4; kc++) {
        qa[kc][0] = *(const unsigned*)&Qs[mw + gr][kc * 16 + gc * 2];
        qa[kc][1] = *(const unsigned*)&Qs[mw + gr + 8][kc * 16 + gc * 2];
        qa[kc][2] = *(const unsigned*)&Qs[mw + gr][kc * 16 + gc * 2 + 8];
        qa[kc][3] = *(const unsigned*)&Qs[mw + gr + 8][kc * 16 + gc * 2 + 8];
    }

    float m0r = -1e30f, m1r = -1e30f, l0 = 0.f, l1 = 0.f;
    float oacc[8][4];
    #pragma unroll
    for (int vn = 0; vn < 8; vn++)
        #pragma unroll
        for (int c = 0; c < 4; c++) oacc[vn][c] = 0.f;

    for (int kt = 0; kt < nkt; kt++) {
        const int st = kt & 1;
        cp_wait<0>();
        __syncthreads();     // tile kt visible; all warps done with buffer st^1
        if (kt + 1 < nkt) {
            size_t kb = (size_t)(b * Ss + (kt + 1) * Gg) * stride + Ee + h * HD_;
            #pragma unroll
            for (int i = 0; i < 4; i++) {
                int t = tid + i * 64; int r = t >> 3, c = (t & 7) * 8;
                cp16(&Ks[st ^ 1][r][c], &qkv[kb + (size_t)r * stride + c]);
                cp16(&Vs[st ^ 1][r][c], &qkv[kb + Ee + (size_t)r * stride + c]);
            }
            cp_commit();
        }

        // ---- S = Q @ K^T ----
        float s[4][4];
        #pragma unroll
        for (int jn = 0; jn < 4; jn++)
            s[jn][0] = s[jn][1] = s[jn][2] = s[jn][3] = 0.f;
        #pragma unroll
        for (int kc = 0; kc < 4; kc++) {
            #pragma unroll
            for (int jn = 0; jn < 4; jn++) {
                unsigned b0 = *(const unsigned*)&Ks[st][jn * 8 + gr][kc * 16 + gc * 2];
                unsigned b1 = *(const unsigned*)&Ks[st][jn * 8 + gr][kc * 16 + gc * 2 + 8];
                mma16816(s[jn], qa[kc], b0, b1);
            }
        }

        // ---- online softmax (rows gr and gr+8) ----
        float mt0 = -1e30f, mt1 = -1e30f;
        #pragma unroll
        for (int jn = 0; jn < 4; jn++) {
            s[jn][0] *= 0.125f; s[jn][1] *= 0.125f;
            s[jn][2] *= 0.125f; s[jn][3] *= 0.125f;
            mt0 = fmaxf(mt0, fmaxf(s[jn][0], s[jn][1]));
            mt1 = fmaxf(mt1, fmaxf(s[jn][2], s[jn][3]));
        }
        mt0 = fmaxf(mt0, __shfl_xor_sync(0xffffffffu, mt0, 1));
        mt0 = fmaxf(mt0, __shfl_xor_sync(0xffffffffu, mt0, 2));
        mt1 = fmaxf(mt1, __shfl_xor_sync(0xffffffffu, mt1, 1));
        mt1 = fmaxf(mt1, __shfl_xor_sync(0xffffffffu, mt1, 2));
        float mn0 = fmaxf(m0r, mt0), mn1 = fmaxf(m1r, mt1);
        float c0 = __expf(m0r - mn0), c1 = __expf(m1r - mn1);
        m0r = mn0; m1r = mn1;
        float rs0 = 0.f, rs1 = 0.f;
        #pragma unroll
        for (int jn = 0; jn < 4; jn++) {
            s[jn][0] = __expf(s[jn][0] - mn0); s[jn][1] = __expf(s[jn][1] - mn0);
            s[jn][2] = __expf(s[jn][2] - mn1); s[jn][3] = __expf(s[jn][3] - mn1);
            rs0 += s[jn][0] + s[jn][1];
            rs1 += s[jn][2] + s[jn][3];
        }
        rs0 += __shfl_xor_sync(0xffffffffu, rs0, 1);
        rs0 += __shfl_xor_sync(0xffffffffu, rs0, 2);
        rs1 += __shfl_xor_sync(0xffffffffu, rs1, 1);
        rs1 += __shfl_xor_sync(0xffffffffu, rs1, 2);
        l0 = l0 * c0 + rs0;
        l1 = l1 * c1 + rs1;

        // ---- P (C-layout) -> fp16 A-fragments ----
        unsigned pa[2][4];
        #pragma unroll
        for (int pc = 0; pc < 2; pc++) {
            __half2 t0 = __floats2half2_rn(s[2 * pc][0],     s[2 * pc][1]);
            __half2 t1 = __floats2half2_rn(s[2 * pc][2],     s[2 * pc][3]);
            __half2 t2 = __floats2half2_rn(s[2 * pc + 1][0], s[2 * pc + 1][1]);
            __half2 t3 = __floats2half2_rn(s[2 * pc + 1][2], s[2 * pc + 1][3]);
            pa[pc][0] = *(unsigned*)&t0; pa[pc][1] = *(unsigned*)&t1;
            pa[pc][2] = *(unsigned*)&t2; pa[pc][3] = *(unsigned*)&t3;
        }

        // ---- O = O*corr + P @ V ----
        #pragma unroll
        for (int vn = 0; vn < 8; vn++) {
            oacc[vn][0] *= c0; oacc[vn][1] *= c0;
            oacc[vn][2] *= c1; oacc[vn][3] *= c1;
        }
        #pragma unroll
        for (int pc = 0; pc < 2; pc++) {
            #pragma unroll
            for (int vn = 0; vn < 8; vn++) {
                unsigned b0, b1;
                ldsm_x2_t(b0, b1, &Vs[st][pc * 16 + (lane & 15)][vn * 8]);
                mma16816(oacc[vn], pa[pc], b0, b1);
            }
        }
    }

    // ---- epilogue ----
    float inv0 = 1.f / l0, inv1 = 1.f / l1;
    size_t r0 = (size_t)(b * Ss + q0 + mw + gr) * Ee + h * HD_;
    size_t r1 = r0 + (size_t)8 * Ee;
    #pragma unroll
    for (int vn = 0; vn < 8; vn++) {
        int col = vn * 8 + gc * 2;
        *(__half2*)&out[r0 + col] = __floats2half2_rn(oacc[vn][0] * inv0, oacc[vn][1] * inv0);
        *(__half2*)&out[r1 + col] = __floats2half2_rn(oacc[vn][2] * inv1, oacc[vn][3] * inv1);
    }
}

// ---------------- host orchestration -----------------------------------------
extern "C" void kernel_launch(void* const* d_in, const int* in_sizes, int n_in,
                              void* d_out, int out_size) {
    const float* x      = (const float*)d_in[0];
    const int*   date   = (const int*)  d_in[1];
    const float* wpe    = (const float*)d_in[2];
    const float* ln1_w  = (const float*)d_in[3];
    const float* ln1_b  = (const float*)d_in[4];
    const float* in_w   = (const float*)d_in[5];
    const float* in_b   = (const float*)d_in[6];
    const float* out_w  = (const float*)d_in[7];
    const float* out_b  = (const float*)d_in[8];
    const float* ln2_w  = (const float*)d_in[9];
    const float* ln2_b  = (const float*)d_in[10];
    const float* fc_w   = (const float*)d_in[11];
    const float* fc_b   = (const float*)d_in[12];
    const float* proj_w = (const float*)d_in[13];
    const float* proj_b = (const float*)d_in[14];
    const float* lnf_w  = (const float*)d_in[15];
    const float* lnf_b  = (const float*)d_in[16];
    float* out = (float*)d_out;

    float  *h;
    __half *y, *qkv, *fc, *wh;
    cudaGetSymbolAddress((void**)&h,   g_h);
    cudaGetSymbolAddress((void**)&y,   g_y);
    cudaGetSymbolAddress((void**)&qkv, g_qkv);
    cudaGetSymbolAddress((void**)&fc,  g_fc);
    cudaGetSymbolAddress((void**)&wh,  g_wh);

    __half* in_wh   = wh;
    __half* out_wh  = wh + W_IN_CNT;
    __half* fc_wh   = wh + W_IN_CNT + W_OUT_CNT;
    __half* proj_wh = wh + W_IN_CNT + W_OUT_CNT + W_FC_CNT;

    f2h4_kernel<<<(W_IN_CNT / 4 + 255) / 256, 256>>>(in_w, in_wh, W_IN_CNT / 4);
    f2h4_kernel<<<(W_OUT_CNT / 4 + 255) / 256, 256>>>(out_w, out_wh, W_OUT_CNT / 4);
    f2h4_kernel<<<(W_FC_CNT / 4 + 255) / 256, 256>>>(fc_w, fc_wh, W_FC_CNT / 4);
    f2h4_kernel<<<(W_PROJ_CNT / 4 + 255) / 256, 256>>>(proj_w, proj_wh, W_PROJ_CNT / 4);

    embed_kernel<<<(NR * Ee + 255) / 256, 256>>>(x, date, wpe);

    for (int l = 0; l < Ll; l++) {
        ln_kernel<__half><<<NR, 256>>>(h, y, ln1_w + (size_t)l * Ee, ln1_b + (size_t)l * Ee);
        gemm_h<4, 0><<<dim3(3 * Ee / 256, NR / 128), 256>>>(
            y, in_wh + (size_t)l * 3 * Ee * Ee, in_b + (size_t)l * 3 * Ee, qkv,
            NR, 3 * Ee, Ee);
        attn_mma<<<dim3(Tt, Hh, Bb), 64>>>(qkv, y);
        gemm_h<2, 2><<<dim3(Ee / 128, NR / 128), 128>>>(
            y, out_wh + (size_t)l * Ee * Ee, out_b + (size_t)l * Ee, h,
            NR, Ee, Ee);
        ln_kernel<__half><<<NR, 256>>>(h, y, ln2_w + (size_t)l * Ee, ln2_b + (size_t)l * Ee);
        gemm_h<4, 1><<<dim3(4 * Ee / 256, NR / 128), 256>>>(
            y, fc_wh + (size_t)l * 4 * Ee * Ee, fc_b + (size_t)l * 4 * Ee, fc,
            NR, 4 * Ee, Ee);
        gemm_h<2, 2><<<dim3(Ee / 128, NR / 128), 128>>>(
            fc, proj_wh + (size_t)l * Ee * 4 * Ee, proj_b + (size_t)l * Ee, h,
            NR, Ee, 4 * Ee);
    }

    ln_kernel<float><<<NR, 256>>>(h, out, lnf_w, lnf_b);
}

// round 13
// speedup vs baseline: 9.3933x; 1.1150x over previous
#include <cuda_runtime.h>
#include <cuda_fp16.h>
#include <math.h>
#include <stdint.h>

#define Bb 8
#define Tt 32
#define Gg 32
#define Ee 768
#define Hh 12
#define Ll 4
#define Ss (Tt*Gg)        // 1024
#define HD_ (Ee/Hh)       // 64
#define NR (Bb*Ss)        // 8192 rows

// weight (half) buffer offsets
#define W_IN_CNT   (Ll*3*Ee*Ee)
#define W_OUT_CNT  (Ll*Ee*Ee)
#define W_FC_CNT   (Ll*4*Ee*Ee)
#define W_PROJ_CNT (Ll*Ee*4*Ee)

// ---------------- scratch (device globals; no cudaMalloc allowed) ------------
__device__ float  g_h[NR*Ee];             // residual stream (fp32)
__device__ __half g_y[NR*Ee];             // ln / attn output (fp16)
__device__ __half g_qkv[NR*3*Ee];         // qkv (fp16)
__device__ __half g_fc[NR*4*Ee];          // mlp hidden (fp16)
__device__ __half g_wh[W_IN_CNT + W_OUT_CNT + W_FC_CNT + W_PROJ_CNT];

// ---------------- fp32 -> fp16 weight conversion ------------------------------
__global__ void f2h4_kernel(const float* __restrict__ in, __half* __restrict__ out, int n4) {
    int i = blockIdx.x * blockDim.x + threadIdx.x;
    if (i >= n4) return;
    float4 v = ((const float4*)in)[i];
    __half2 a = __floats2half2_rn(v.x, v.y);
    __half2 b = __floats2half2_rn(v.z, v.w);
    ((__half2*)out)[i * 2]     = a;
    ((__half2*)out)[i * 2 + 1] = b;
}

// ---------------- embed -------------------------------------------------------
__global__ void embed_kernel(const float* __restrict__ x,
                             const int* __restrict__ date,
                             const float* __restrict__ wpe) {
    int idx = blockIdx.x * blockDim.x + threadIdx.x;
    if (idx >= NR * Ee) return;
    int e   = idx % Ee;
    int row = idx / Ee;
    int b   = row / Ss;
    int s   = row % Ss;
    int t   = s / Gg;
    int d   = date[b * Tt + t];
    d = min(max(d, 0), 49);
    g_h[idx] = x[idx] + wpe[d * Ee + e];
}

// ---------------- layernorm: 256 thr, single pass, shuffle reduction ----------
template<typename OT>
__global__ void __launch_bounds__(256)
ln_kernel(const float* __restrict__ in, OT* __restrict__ out,
          const float* __restrict__ w, const float* __restrict__ bia) {
    const int row = blockIdx.x;
    const int tid = threadIdx.x;
    const float* xr = in + (size_t)row * Ee;
    float x0 = xr[tid], x1 = xr[tid + 256], x2 = xr[tid + 512];
    float s = x0 + x1 + x2;
    float q = x0 * x0 + x1 * x1 + x2 * x2;
    #pragma unroll
    for (int o = 16; o > 0; o >>= 1) {
        s += __shfl_xor_sync(0xffffffffu, s, o);
        q += __shfl_xor_sync(0xffffffffu, q, o);
    }
    __shared__ float sw[8], qw[8];
    if ((tid & 31) == 0) { sw[tid >> 5] = s; qw[tid >> 5] = q; }
    __syncthreads();
    s = sw[0] + sw[1] + sw[2] + sw[3] + sw[4] + sw[5] + sw[6] + sw[7];
    q = qw[0] + qw[1] + qw[2] + qw[3] + qw[4] + qw[5] + qw[6] + qw[7];
    const float inv = 1.0f / Ee;
    float mean = s * inv;
    float var  = q * inv - mean * mean;
    float rstd = rsqrtf(var + 1e-5f);
    OT* orow = out + (size_t)row * Ee;
    orow[tid]       = (OT)((x0 - mean) * rstd * w[tid]       + bia[tid]);
    orow[tid + 256] = (OT)((x1 - mean) * rstd * w[tid + 256] + bia[tid + 256]);
    orow[tid + 512] = (OT)((x2 - mean) * rstd * w[tid + 512] + bia[tid + 512]);
}

// ---------------- cp.async helpers -------------------------------------------
__device__ __forceinline__ void cp16(void* s, const void* g) {
    unsigned sa = (unsigned)__cvta_generic_to_shared(s);
    asm volatile("cp.async.ca.shared.global [%0], [%1], 16;\n" :: "r"(sa), "l"(g));
}
__device__ __forceinline__ void cp_commit() {
    asm volatile("cp.async.commit_group;\n" ::);
}
template<int N>
__device__ __forceinline__ void cp_wait() {
    asm volatile("cp.async.wait_group %0;\n" :: "n"(N));
}

// ---------------- mma / ldmatrix helpers --------------------------------------
__device__ __forceinline__ void mma16816(float c[4], const unsigned a[4],
                                         unsigned b0, unsigned b1) {
    asm volatile("mma.sync.aligned.m16n8k16.row.col.f32.f16.f16.f32 "
                 "{%0,%1,%2,%3}, {%4,%5,%6,%7}, {%8,%9}, {%0,%1,%2,%3};"
                 : "+f"(c[0]), "+f"(c[1]), "+f"(c[2]), "+f"(c[3])
                 : "r"(a[0]), "r"(a[1]), "r"(a[2]), "r"(a[3]), "r"(b0), "r"(b1));
}
__device__ __forceinline__ void ldsm_x4(unsigned &r0, unsigned &r1, unsigned &r2,
                                        unsigned &r3, unsigned addr) {
    asm volatile("ldmatrix.sync.aligned.m8n8.x4.shared.b16 {%0,%1,%2,%3}, [%4];"
                 : "=r"(r0), "=r"(r1), "=r"(r2), "=r"(r3) : "r"(addr));
}
__device__ __forceinline__ void ldsm_x2_t(unsigned &r0, unsigned &r1, const void* p) {
    unsigned a = (unsigned)__cvta_generic_to_shared(p);
    asm volatile("ldmatrix.sync.aligned.m8n8.x2.trans.shared.b16 {%0,%1}, [%2];"
                 : "=r"(r0), "=r"(r1) : "r"(a));
}

// ---------------- fp16 HMMA GEMM, BK=64, SW128 smem + ldmatrix operands -------
// C[m,n] (op)= sum_k A[m,k]*W[n,k] + bias[n];  A,W fp16 K-major; fp32 acc.
// BM=128, BN=WN*64, threads=WN*64 (2 x WN warps), warp tile 64x64.
// smem: 128B rows (64 halfs), chunk^= (row&7) swizzle; 2-stage cp.async.
// EPI: 0 = store half, 1 = NewGELU -> half, 2 = add fp32 into C (residual)
template<int WN, int EPI>
__global__ void __launch_bounds__(WN * 64)
gemm_h(const __half* __restrict__ A, const __half* __restrict__ W,
       const float* __restrict__ bias, void* __restrict__ Cv,
       int M, int N, int K) {
    constexpr int BN  = WN * 64;
    constexpr int NTH = WN * 64;
    constexpr unsigned ASTAGE = 16384u;          // 128 rows * 128 B
    constexpr unsigned WOFF   = 2 * ASTAGE;      // A stages end
    constexpr unsigned WSTAGE = (unsigned)BN * 128u;
    extern __shared__ __align__(128) char sm[];
    const unsigned sb = (unsigned)__cvta_generic_to_shared(sm);

    const int m0 = blockIdx.y * 128;
    const int n0 = blockIdx.x * BN;
    const int tid  = threadIdx.x;
    const int lane = tid & 31;
    const int wid  = tid >> 5;
    const int wm = (wid & 1) * 64;
    const int wn = (wid >> 1) * 64;
    const int gr = lane >> 2;
    const int gc = lane & 3;

    // ldmatrix per-lane geometry
    const int g = lane >> 3, j = lane & 7;
    const int arowoff = ((g & 1) << 3) + j;      // A: row-in-16 tile
    const int acoff   = g >> 1;                  // A: +chunk
    const int browoff = ((g >> 1) << 3) + j;     // B: row-in-16 pair
    const int bcoff   = g & 1;                   // B: +chunk

    const int KT = K >> 6;

    float acc[4][8][4];
    #pragma unroll
    for (int tm = 0; tm < 4; tm++)
        #pragma unroll
        for (int tn = 0; tn < 8; tn++)
            #pragma unroll
            for (int i = 0; i < 4; i++) acc[tm][tn][i] = 0.f;

    #define LOAD_TILE(st, kt_) do {                                               \
        int k0 = (kt_) << 6;                                                      \
        _Pragma("unroll")                                                         \
        for (int i = tid; i < (128 + BN) * 8; i += NTH) {                         \
            int r = i >> 3, c = i & 7;                                            \
            if (r < 128) {                                                        \
                cp16(sm + (st) * ASTAGE + r * 128 + ((c ^ (r & 7)) * 16),         \
                     &A[(size_t)(m0 + r) * K + k0 + c * 8]);                      \
            } else {                                                              \
                int rr = r - 128;                                                 \
                cp16(sm + WOFF + (st) * WSTAGE + rr * 128 + ((c ^ (rr & 7)) * 16),\
                     &W[(size_t)(n0 + rr) * K + k0 + c * 8]);                     \
            }                                                                     \
        }                                                                         \
    } while (0)

    LOAD_TILE(0, 0); cp_commit();
    if (KT > 1) LOAD_TILE(1, 1);
    cp_commit();

    for (int kt = 0; kt < KT; kt++) {
        const int st = kt & 1;
        cp_wait<1>();
        __syncthreads();
        const unsigned aSt = sb + st * ASTAGE;
        const unsigned wSt = sb + WOFF + st * WSTAGE;

        #pragma unroll
        for (int kk = 0; kk < 64; kk += 16) {
            const int cbase = kk >> 3;
            unsigned af[4][4], bf[8][2];
            #pragma unroll
            for (int tm = 0; tm < 4; tm++) {
                int row = wm + tm * 16 + arowoff;
                unsigned addr = aSt + row * 128 + (((cbase + acoff) ^ (row & 7)) << 4);
                ldsm_x4(af[tm][0], af[tm][1], af[tm][2], af[tm][3], addr);
            }
            #pragma unroll
            for (int tp = 0; tp < 4; tp++) {
                int row = wn + tp * 16 + browoff;
                unsigned addr = wSt + row * 128 + (((cbase + bcoff) ^ (row & 7)) << 4);
                ldsm_x4(bf[2 * tp][0], bf[2 * tp][1], bf[2 * tp + 1][0], bf[2 * tp + 1][1], addr);
            }
            #pragma unroll
            for (int tm = 0; tm < 4; tm++)
                #pragma unroll
                for (int tn = 0; tn < 8; tn++)
                    mma16816(acc[tm][tn], af[tm], bf[tn][0], bf[tn][1]);
        }
        __syncthreads();
        if (kt + 2 < KT) LOAD_TILE(st, kt + 2);
        cp_commit();
    }
    #undef LOAD_TILE

    #pragma unroll
    for (int tm = 0; tm < 4; tm++) {
        #pragma unroll
        for (int tn = 0; tn < 8; tn++) {
            int m = m0 + wm + tm * 16 + gr;
            int n = n0 + wn + tn * 8 + gc * 2;
            float b0 = bias[n], b1 = bias[n + 1];
            #pragma unroll
            for (int half_ = 0; half_ < 2; half_++) {
                int mm = m + half_ * 8;
                float v0 = acc[tm][tn][half_ * 2 + 0] + b0;
                float v1 = acc[tm][tn][half_ * 2 + 1] + b1;
                size_t o = (size_t)mm * N + n;
                if (EPI == 0) {
                    *(__half2*)((__half*)Cv + o) = __floats2half2_rn(v0, v1);
                } else if (EPI == 1) {
                    float u0 = v0 + 0.044715f * v0 * v0 * v0;
                    float u1 = v1 + 0.044715f * v1 * v1 * v1;
                    float g0 = 0.5f * v0 * (1.0f + tanhf(0.7978845608028654f * u0));
                    float g1 = 0.5f * v1 * (1.0f + tanhf(0.7978845608028654f * u1));
                    *(__half2*)((__half*)Cv + o) = __floats2half2_rn(g0, g1);
                } else {
                    float* C = (float*)Cv;
                    C[o] += v0; C[o + 1] += v1;
                }
            }
        }
    }
}

// ---------------- tensor-core flash attention ---------------------------------
__global__ void __launch_bounds__(64)
attn_mma(const __half* __restrict__ qkv, __half* __restrict__ out) {
    const int tq = (Tt - 1) - blockIdx.x;
    const int h = blockIdx.y, b = blockIdx.z;
    const int q0 = tq * Gg;
    const int nkt = tq + 1;
    const int tid  = threadIdx.x;
    const int lane = tid & 31;
    const int warp = tid >> 5;
    const int gr = lane >> 2, gc = lane & 3;
    const int mw = warp * 16;

    __shared__ __half Qs[32][72];
    __shared__ __half Ks[2][32][72];
    __shared__ __half Vs[2][32][72];

    const size_t stride = 3 * Ee;
    const size_t qbase = (size_t)(b * Ss + q0) * stride + h * HD_;

    {
        size_t kb = (size_t)(b * Ss) * stride + Ee + h * HD_;
        #pragma unroll
        for (int i = 0; i < 4; i++) {
            int t = tid + i * 64; int r = t >> 3, c = (t & 7) * 8;
            cp16(&Ks[0][r][c], &qkv[kb + (size_t)r * stride + c]);
            cp16(&Vs[0][r][c], &qkv[kb + Ee + (size_t)r * stride + c]);
        }
        cp_commit();
    }
    #pragma unroll
    for (int i = 0; i < 4; i++) {
        int t = tid + i * 64; int r = t >> 3, c = (t & 7) * 8;
        *(uint4*)&Qs[r][c] = *(const uint4*)&qkv[qbase + (size_t)r * stride + c];
    }
    __syncthreads();

    unsigned qa[4][4];
    #pragma unroll
    for (int kc = 0; kc < 4; kc++) {
        qa[kc][0] = *(const unsigned*)&Qs[mw + gr][kc * 16 + gc * 2];
        qa[kc][1] = *(const unsigned*)&Qs[mw + gr + 8][kc * 16 + gc * 2];
        qa[kc][2] = *(const unsigned*)&Qs[mw + gr][kc * 16 + gc * 2 + 8];
        qa[kc][3] = *(const unsigned*)&Qs[mw + gr + 8][kc * 16 + gc * 2 + 8];
    }

    float m0r = -1e30f, m1r = -1e30f, l0 = 0.f, l1 = 0.f;
    float oacc[8][4];
    #pragma unroll
    for (int vn = 0; vn < 8; vn++)
        #pragma unroll
        for (int c = 0; c < 4; c++) oacc[vn][c] = 0.f;

    for (int kt = 0; kt < nkt; kt++) {
        const int st = kt & 1;
        cp_wait<0>();
        __syncthreads();
        if (kt + 1 < nkt) {
            size_t kb = (size_t)(b * Ss + (kt + 1) * Gg) * stride + Ee + h * HD_;
            #pragma unroll
            for (int i = 0; i < 4; i++) {
                int t = tid + i * 64; int r = t >> 3, c = (t & 7) * 8;
                cp16(&Ks[st ^ 1][r][c], &qkv[kb + (size_t)r * stride + c]);
                cp16(&Vs[st ^ 1][r][c], &qkv[kb + Ee + (size_t)r * stride + c]);
            }
            cp_commit();
        }

        float s[4][4];
        #pragma unroll
        for (int jn = 0; jn < 4; jn++)
            s[jn][0] = s[jn][1] = s[jn][2] = s[jn][3] = 0.f;
        #pragma unroll
        for (int kc = 0; kc < 4; kc++) {
            #pragma unroll
            for (int jn = 0; jn < 4; jn++) {
                unsigned b0 = *(const unsigned*)&Ks[st][jn * 8 + gr][kc * 16 + gc * 2];
                unsigned b1 = *(const unsigned*)&Ks[st][jn * 8 + gr][kc * 16 + gc * 2 + 8];
                mma16816(s[jn], qa[kc], b0, b1);
            }
        }

        float mt0 = -1e30f, mt1 = -1e30f;
        #pragma unroll
        for (int jn = 0; jn < 4; jn++) {
            s[jn][0] *= 0.125f; s[jn][1] *= 0.125f;
            s[jn][2] *= 0.125f; s[jn][3] *= 0.125f;
            mt0 = fmaxf(mt0, fmaxf(s[jn][0], s[jn][1]));
            mt1 = fmaxf(mt1, fmaxf(s[jn][2], s[jn][3]));
        }
        mt0 = fmaxf(mt0, __shfl_xor_sync(0xffffffffu, mt0, 1));
        mt0 = fmaxf(mt0, __shfl_xor_sync(0xffffffffu, mt0, 2));
        mt1 = fmaxf(mt1, __shfl_xor_sync(0xffffffffu, mt1, 1));
        mt1 = fmaxf(mt1, __shfl_xor_sync(0xffffffffu, mt1, 2));
        float mn0 = fmaxf(m0r, mt0), mn1 = fmaxf(m1r, mt1);
        float c0 = __expf(m0r - mn0), c1 = __expf(m1r - mn1);
        m0r = mn0; m1r = mn1;
        float rs0 = 0.f, rs1 = 0.f;
        #pragma unroll
        for (int jn = 0; jn < 4; jn++) {
            s[jn][0] = __expf(s[jn][0] - mn0); s[jn][1] = __expf(s[jn][1] - mn0);
            s[jn][2] = __expf(s[jn][2] - mn1); s[jn][3] = __expf(s[jn][3] - mn1);
            rs0 += s[jn][0] + s[jn][1];
            rs1 += s[jn][2] + s[jn][3];
        }
        rs0 += __shfl_xor_sync(0xffffffffu, rs0, 1);
        rs0 += __shfl_xor_sync(0xffffffffu, rs0, 2);
        rs1 += __shfl_xor_sync(0xffffffffu, rs1, 1);
        rs1 += __shfl_xor_sync(0xffffffffu, rs1, 2);
        l0 = l0 * c0 + rs0;
        l1 = l1 * c1 + rs1;

        unsigned pa[2][4];
        #pragma unroll
        for (int pc = 0; pc < 2; pc++) {
            __half2 t0 = __floats2half2_rn(s[2 * pc][0],     s[2 * pc][1]);
            __half2 t1 = __floats2half2_rn(s[2 * pc][2],     s[2 * pc][3]);
            __half2 t2 = __floats2half2_rn(s[2 * pc + 1][0], s[2 * pc + 1][1]);
            __half2 t3 = __floats2half2_rn(s[2 * pc + 1][2], s[2 * pc + 1][3]);
            pa[pc][0] = *(unsigned*)&t0; pa[pc][1] = *(unsigned*)&t1;
            pa[pc][2] = *(unsigned*)&t2; pa[pc][3] = *(unsigned*)&t3;
        }

        #pragma unroll
        for (int vn = 0; vn < 8; vn++) {
            oacc[vn][0] *= c0; oacc[vn][1] *= c0;
            oacc[vn][2] *= c1; oacc[vn][3] *= c1;
        }
        #pragma unroll
        for (int pc = 0; pc < 2; pc++) {
            #pragma unroll
            for (int vn = 0; vn < 8; vn++) {
                unsigned b0, b1;
                ldsm_x2_t(b0, b1, &Vs[st][pc * 16 + (lane & 15)][vn * 8]);
                mma16816(oacc[vn], pa[pc], b0, b1);
            }
        }
    }

    float inv0 = 1.f / l0, inv1 = 1.f / l1;
    size_t r0 = (size_t)(b * Ss + q0 + mw + gr) * Ee + h * HD_;
    size_t r1 = r0 + (size_t)8 * Ee;
    #pragma unroll
    for (int vn = 0; vn < 8; vn++) {
        int col = vn * 8 + gc * 2;
        *(__half2*)&out[r0 + col] = __floats2half2_rn(oacc[vn][0] * inv0, oacc[vn][1] * inv0);
        *(__half2*)&out[r1 + col] = __floats2half2_rn(oacc[vn][2] * inv1, oacc[vn][3] * inv1);
    }
}

// ---------------- host orchestration -----------------------------------------
extern "C" void kernel_launch(void* const* d_in, const int* in_sizes, int n_in,
                              void* d_out, int out_size) {
    const float* x      = (const float*)d_in[0];
    const int*   date   = (const int*)  d_in[1];
    const float* wpe    = (const float*)d_in[2];
    const float* ln1_w  = (const float*)d_in[3];
    const float* ln1_b  = (const float*)d_in[4];
    const float* in_w   = (const float*)d_in[5];
    const float* in_b   = (const float*)d_in[6];
    const float* out_w  = (const float*)d_in[7];
    const float* out_b  = (const float*)d_in[8];
    const float* ln2_w  = (const float*)d_in[9];
    const float* ln2_b  = (const float*)d_in[10];
    const float* fc_w   = (const float*)d_in[11];
    const float* fc_b   = (const float*)d_in[12];
    const float* proj_w = (const float*)d_in[13];
    const float* proj_b = (const float*)d_in[14];
    const float* lnf_w  = (const float*)d_in[15];
    const float* lnf_b  = (const float*)d_in[16];
    float* out = (float*)d_out;

    float  *h;
    __half *y, *qkv, *fc, *wh;
    cudaGetSymbolAddress((void**)&h,   g_h);
    cudaGetSymbolAddress((void**)&y,   g_y);
    cudaGetSymbolAddress((void**)&qkv, g_qkv);
    cudaGetSymbolAddress((void**)&fc,  g_fc);
    cudaGetSymbolAddress((void**)&wh,  g_wh);

    __half* in_wh   = wh;
    __half* out_wh  = wh + W_IN_CNT;
    __half* fc_wh   = wh + W_IN_CNT + W_OUT_CNT;
    __half* proj_wh = wh + W_IN_CNT + W_OUT_CNT + W_FC_CNT;

    // dynamic smem: wide (WN=4) = 2*16384 + 2*256*128 = 98304; narrow = 65536
    const int SMEM_WIDE = 98304, SMEM_NARROW = 65536;
    cudaFuncSetAttribute(gemm_h<4, 0>, cudaFuncAttributeMaxDynamicSharedMemorySize, SMEM_WIDE);
    cudaFuncSetAttribute(gemm_h<4, 1>, cudaFuncAttributeMaxDynamicSharedMemorySize, SMEM_WIDE);
    cudaFuncSetAttribute(gemm_h<2, 2>, cudaFuncAttributeMaxDynamicSharedMemorySize, SMEM_NARROW);

    f2h4_kernel<<<(W_IN_CNT / 4 + 255) / 256, 256>>>(in_w, in_wh, W_IN_CNT / 4);
    f2h4_kernel<<<(W_OUT_CNT / 4 + 255) / 256, 256>>>(out_w, out_wh, W_OUT_CNT / 4);
    f2h4_kernel<<<(W_FC_CNT / 4 + 255) / 256, 256>>>(fc_w, fc_wh, W_FC_CNT / 4);
    f2h4_kernel<<<(W_PROJ_CNT / 4 + 255) / 256, 256>>>(proj_w, proj_wh, W_PROJ_CNT / 4);

    embed_kernel<<<(NR * Ee + 255) / 256, 256>>>(x, date, wpe);

    for (int l = 0; l < Ll; l++) {
        ln_kernel<__half><<<NR, 256>>>(h, y, ln1_w + (size_t)l * Ee, ln1_b + (size_t)l * Ee);
        gemm_h<4, 0><<<dim3(3 * Ee / 256, NR / 128), 256, SMEM_WIDE>>>(
            y, in_wh + (size_t)l * 3 * Ee * Ee, in_b + (size_t)l * 3 * Ee, qkv,
            NR, 3 * Ee, Ee);
        attn_mma<<<dim3(Tt, Hh, Bb), 64>>>(qkv, y);
        gemm_h<2, 2><<<dim3(Ee / 128, NR / 128), 128, SMEM_NARROW>>>(
            y, out_wh + (size_t)l * Ee * Ee, out_b + (size_t)l * Ee, h,
            NR, Ee, Ee);
        ln_kernel<__half><<<NR, 256>>>(h, y, ln2_w + (size_t)l * Ee, ln2_b + (size_t)l * Ee);
        gemm_h<4, 1><<<dim3(4 * Ee / 256, NR / 128), 256, SMEM_WIDE>>>(
            y, fc_wh + (size_t)l * 4 * Ee * Ee, fc_b + (size_t)l * 4 * Ee, fc,
            NR, 4 * Ee, Ee);
        gemm_h<2, 2><<<dim3(Ee / 128, NR / 128), 128, SMEM_NARROW>>>(
            fc, proj_wh + (size_t)l * Ee * 4 * Ee, proj_b + (size_t)l * Ee, h,
            NR, Ee, 4 * Ee);
    }

    ln_kernel<float><<<NR, 256>>>(h, out, lnf_w, lnf_b);
}